// round 1
// baseline (speedup 1.0000x reference)
#include <cuda_runtime.h>
#include <math.h>

#define D_MODEL 2048
#define T_SEQ   2048
#define N_HEADS 16
#define D_HEAD  128
#define BT_MAX  4096   // B=2 * T=2048

// ---------------- scratch (device globals; allocation-free) ----------------
__device__ float g_q[(size_t)BT_MAX * D_MODEL];
__device__ float g_k[(size_t)BT_MAX * D_MODEL];
__device__ float g_v[(size_t)BT_MAX * D_MODEL];
__device__ float g_attn[(size_t)BT_MAX * D_MODEL];

// ---------------- GEMM: C[M,N] = A[M,K] @ B[N,K]^T + bias[N] ----------------
#define GM 128
#define GN 128
#define GK 8
#define ASTR 132  // padded row stride (floats) for conflict-free smem

__global__ __launch_bounds__(256) void gemm_nt_bias(
    const float* __restrict__ A, const float* __restrict__ Bm,
    const float* __restrict__ bias, float* __restrict__ C,
    int M, int N, int K)
{
    __shared__ float As[GK][ASTR];
    __shared__ float Bs[GK][ASTR];

    const int tid = threadIdx.x;
    const int bm = blockIdx.y, bn = blockIdx.x;
    const int ty = tid >> 4, tx = tid & 15;
    const int r0 = ty * 8, c0 = tx * 8;

    const int lr = tid >> 1;        // 0..127
    const int lk = (tid & 1) * 4;   // 0 or 4

    const float* Ap = A + (size_t)(bm * GM + lr) * K + lk;
    const float* Bp = Bm + (size_t)(bn * GN + lr) * K + lk;

    float acc[8][8];
#pragma unroll
    for (int i = 0; i < 8; i++)
#pragma unroll
        for (int j = 0; j < 8; j++) acc[i][j] = 0.f;

    float4 av = *(const float4*)(Ap);
    float4 bv = *(const float4*)(Bp);

    for (int k0 = 0; k0 < K; k0 += GK) {
        As[lk + 0][lr] = av.x; As[lk + 1][lr] = av.y;
        As[lk + 2][lr] = av.z; As[lk + 3][lr] = av.w;
        Bs[lk + 0][lr] = bv.x; Bs[lk + 1][lr] = bv.y;
        Bs[lk + 2][lr] = bv.z; Bs[lk + 3][lr] = bv.w;
        __syncthreads();

        if (k0 + GK < K) {
            av = *(const float4*)(Ap + k0 + GK);
            bv = *(const float4*)(Bp + k0 + GK);
        }

#pragma unroll
        for (int k = 0; k < GK; ++k) {
            float a[8], b[8];
            *(float4*)(a)     = *(const float4*)&As[k][r0];
            *(float4*)(a + 4) = *(const float4*)&As[k][r0 + 4];
            *(float4*)(b)     = *(const float4*)&Bs[k][c0];
            *(float4*)(b + 4) = *(const float4*)&Bs[k][c0 + 4];
#pragma unroll
            for (int i = 0; i < 8; i++)
#pragma unroll
                for (int j = 0; j < 8; j++)
                    acc[i][j] += a[i] * b[j];
        }
        __syncthreads();
    }

    // epilogue: add bias, write
    float bvals[8];
#pragma unroll
    for (int j = 0; j < 8; j++) bvals[j] = bias[bn * GN + c0 + j];

#pragma unroll
    for (int i = 0; i < 8; i++) {
        float* Cp = C + (size_t)(bm * GM + r0 + i) * N + bn * GN + c0;
        float4 o0, o1;
        o0.x = acc[i][0] + bvals[0]; o0.y = acc[i][1] + bvals[1];
        o0.z = acc[i][2] + bvals[2]; o0.w = acc[i][3] + bvals[3];
        o1.x = acc[i][4] + bvals[4]; o1.y = acc[i][5] + bvals[5];
        o1.z = acc[i][6] + bvals[6]; o1.w = acc[i][7] + bvals[7];
        *(float4*)(Cp) = o0;
        *(float4*)(Cp + 4) = o1;
    }
}

// ---------------- fused RMSNorm (over D=2048) + interleaved RoPE ----------------
__global__ __launch_bounds__(256) void rmsnorm_rope(
    float* __restrict__ h, const float* __restrict__ w,
    const float* __restrict__ cosb, const float* __restrict__ sinb)
{
    const int row = blockIdx.x;
    const int t = row & (T_SEQ - 1);
    float* hp = h + (size_t)row * D_MODEL;
    const float* cp = cosb + (size_t)t * D_MODEL;
    const float* sp = sinb + (size_t)t * D_MODEL;
    const int tid = threadIdx.x;

    float4 vals[2];
    float ss = 0.f;
#pragma unroll
    for (int i = 0; i < 2; i++) {
        float4 v = ((const float4*)hp)[tid + i * 256];
        vals[i] = v;
        ss += v.x * v.x + v.y * v.y + v.z * v.z + v.w * v.w;
    }
    // block reduce
#pragma unroll
    for (int o = 16; o > 0; o >>= 1) ss += __shfl_xor_sync(0xffffffffu, ss, o);
    __shared__ float red[8];
    __shared__ float s_inv;
    if ((tid & 31) == 0) red[tid >> 5] = ss;
    __syncthreads();
    if (tid == 0) {
        float tot = 0.f;
#pragma unroll
        for (int i = 0; i < 8; i++) tot += red[i];
        s_inv = rsqrtf(tot * (1.0f / D_MODEL) + 1e-6f);
    }
    __syncthreads();
    const float inv = s_inv;

#pragma unroll
    for (int i = 0; i < 2; i++) {
        int fi = tid + i * 256;
        float4 v = vals[i];
        float4 wv = ((const float4*)w)[fi];
        float4 c4 = ((const float4*)cp)[fi];
        float4 s4 = ((const float4*)sp)[fi];
        float nx = v.x * inv * wv.x;
        float ny = v.y * inv * wv.y;
        float nz = v.z * inv * wv.z;
        float nw = v.w * inv * wv.w;
        float4 o;
        o.x = nx * c4.x - ny * s4.x;   // even: h*cos - odd*sin
        o.y = ny * c4.y + nx * s4.y;   // odd:  h*cos + even*sin
        o.z = nz * c4.z - nw * s4.z;
        o.w = nw * c4.w + nz * s4.w;
        ((float4*)hp)[fi] = o;
    }
}

// ---------------- flash attention (fp32, non-causal) ----------------
#define BQ  64
#define BKT 64
#define PSTR 68

__global__ __launch_bounds__(256) void attn_kernel(
    const float* __restrict__ Q, const float* __restrict__ Kg,
    const float* __restrict__ Vg, float* __restrict__ Og)
{
    extern __shared__ float smem[];
    float* Qs = smem;                         // [128][64]  Qs[d*64 + r], pre-scaled
    float* Ks = Qs + D_HEAD * BQ;             // [128][64]  Ks[d*64 + c]
    float* Vs = Ks + D_HEAD * BKT;            // [64][128]  Vs[kk*128 + d]
    float* Ps = Vs + BKT * D_HEAD;            // [64][PSTR] Ps[kk*PSTR + r]
    float* m_s = Ps + BKT * PSTR;
    float* l_s = m_s + BQ;
    float* corr_s = l_s + BQ;

    const int tid = threadIdx.x;
    const int h = blockIdx.y, b = blockIdx.z;
    const int q0 = blockIdx.x * BQ;
    const size_t rowbase = (size_t)b * T_SEQ;
    const float scale = 0.08838834764831845f;  // 1/sqrt(128)

    const int r0 = (tid >> 4) * 4;   // S/PV rows (4)
    const int c0 = (tid & 15) * 4;   // S cols (4)
    const int oc0 = (tid & 15) * 8;  // O cols (8)

    // ---- load Q tile (transposed, scaled) ----
#pragma unroll
    for (int i = 0; i < 8; i++) {
        int s = tid + i * 256;
        int d4 = s >> 6;      // 0..31
        int r = s & 63;
        float4 v = *(const float4*)(Q + (rowbase + q0 + r) * D_MODEL + h * D_HEAD + d4 * 4);
        Qs[(4 * d4 + 0) * BQ + r] = v.x * scale;
        Qs[(4 * d4 + 1) * BQ + r] = v.y * scale;
        Qs[(4 * d4 + 2) * BQ + r] = v.z * scale;
        Qs[(4 * d4 + 3) * BQ + r] = v.w * scale;
    }
    if (tid < BQ) { m_s[tid] = -1e30f; l_s[tid] = 0.f; }

    float Oacc[4][8];
#pragma unroll
    for (int i = 0; i < 4; i++)
#pragma unroll
        for (int j = 0; j < 8; j++) Oacc[i][j] = 0.f;

    for (int kt = 0; kt < T_SEQ; kt += BKT) {
        __syncthreads();  // previous PV done before overwriting Ks/Vs

        // ---- load K tile (transposed) ----
#pragma unroll
        for (int i = 0; i < 8; i++) {
            int s = tid + i * 256;
            int d4 = s >> 6;
            int c = s & 63;
            float4 v = *(const float4*)(Kg + (rowbase + kt + c) * D_MODEL + h * D_HEAD + d4 * 4);
            Ks[(4 * d4 + 0) * BKT + c] = v.x;
            Ks[(4 * d4 + 1) * BKT + c] = v.y;
            Ks[(4 * d4 + 2) * BKT + c] = v.z;
            Ks[(4 * d4 + 3) * BKT + c] = v.w;
        }
        // ---- load V tile (natural) ----
#pragma unroll
        for (int i = 0; i < 8; i++) {
            int s = tid + i * 256;
            int kk = s >> 5;
            int d4 = s & 31;
            float4 v = *(const float4*)(Vg + (rowbase + kt + kk) * D_MODEL + h * D_HEAD + d4 * 4);
            *(float4*)&Vs[kk * D_HEAD + d4 * 4] = v;
        }
        __syncthreads();

        // ---- S = Qs^T Ks (4x4 per thread) ----
        float Sacc[4][4];
#pragma unroll
        for (int i = 0; i < 4; i++)
#pragma unroll
            for (int j = 0; j < 4; j++) Sacc[i][j] = 0.f;

#pragma unroll 4
        for (int d = 0; d < D_HEAD; d++) {
            float4 qa = *(const float4*)&Qs[d * BQ + r0];
            float4 kb = *(const float4*)&Ks[d * BKT + c0];
            float a[4] = {qa.x, qa.y, qa.z, qa.w};
            float bb[4] = {kb.x, kb.y, kb.z, kb.w};
#pragma unroll
            for (int i = 0; i < 4; i++)
#pragma unroll
                for (int j = 0; j < 4; j++)
                    Sacc[i][j] += a[i] * bb[j];
        }
        // write S -> Ps[kk][r]
#pragma unroll
        for (int j = 0; j < 4; j++) {
            float4 col = make_float4(Sacc[0][j], Sacc[1][j], Sacc[2][j], Sacc[3][j]);
            *(float4*)&Ps[(c0 + j) * PSTR + r0] = col;
        }
        __syncthreads();

        // ---- online softmax per row (64 threads) ----
        if (tid < BQ) {
            int r = tid;
            float m_old = m_s[r];
            float mx = m_old;
#pragma unroll 8
            for (int c = 0; c < BKT; c++) mx = fmaxf(mx, Ps[c * PSTR + r]);
            float corr = __expf(m_old - mx);
            float sum = 0.f;
#pragma unroll 8
            for (int c = 0; c < BKT; c++) {
                float p = __expf(Ps[c * PSTR + r] - mx);
                Ps[c * PSTR + r] = p;
                sum += p;
            }
            l_s[r] = l_s[r] * corr + sum;
            m_s[r] = mx;
            corr_s[r] = corr;
        }
        __syncthreads();

        // ---- rescale O, accumulate PV ----
#pragma unroll
        for (int i = 0; i < 4; i++) {
            float corr = corr_s[r0 + i];
#pragma unroll
            for (int j = 0; j < 8; j++) Oacc[i][j] *= corr;
        }
#pragma unroll 2
        for (int kk = 0; kk < BKT; kk++) {
            float4 p4 = *(const float4*)&Ps[kk * PSTR + r0];
            float4 va = *(const float4*)&Vs[kk * D_HEAD + oc0];
            float4 vb = *(const float4*)&Vs[kk * D_HEAD + oc0 + 4];
            float p[4] = {p4.x, p4.y, p4.z, p4.w};
            float vv[8] = {va.x, va.y, va.z, va.w, vb.x, vb.y, vb.z, vb.w};
#pragma unroll
            for (int i = 0; i < 4; i++)
#pragma unroll
                for (int j = 0; j < 8; j++)
                    Oacc[i][j] += p[i] * vv[j];
        }
    }

    // ---- finalize: O /= l, write out ----
    __syncthreads();
#pragma unroll
    for (int i = 0; i < 4; i++) {
        float linv = 1.0f / l_s[r0 + i];
        float* Op = Og + (rowbase + q0 + r0 + i) * D_MODEL + h * D_HEAD + oc0;
        float4 o0, o1;
        o0.x = Oacc[i][0] * linv; o0.y = Oacc[i][1] * linv;
        o0.z = Oacc[i][2] * linv; o0.w = Oacc[i][3] * linv;
        o1.x = Oacc[i][4] * linv; o1.y = Oacc[i][5] * linv;
        o1.z = Oacc[i][6] * linv; o1.w = Oacc[i][7] * linv;
        *(float4*)(Op) = o0;
        *(float4*)(Op + 4) = o1;
    }
}

// ---------------- host launch ----------------
extern "C" void kernel_launch(void* const* d_in, const int* in_sizes, int n_in,
                              void* d_out, int out_size)
{
    const float* x   = (const float*)d_in[0];
    const float* cosb= (const float*)d_in[1];
    const float* sinb= (const float*)d_in[2];
    const float* Wq  = (const float*)d_in[3];
    const float* bq  = (const float*)d_in[4];
    const float* Wk  = (const float*)d_in[5];
    const float* bk  = (const float*)d_in[6];
    const float* Wv  = (const float*)d_in[7];
    const float* bv  = (const float*)d_in[8];
    const float* qnw = (const float*)d_in[9];
    const float* knw = (const float*)d_in[10];
    const float* Wo  = (const float*)d_in[11];
    const float* bo  = (const float*)d_in[12];
    float* out = (float*)d_out;

    const int BT = in_sizes[0] / D_MODEL;    // B*T = 4096
    const int Bb = BT / T_SEQ;               // batch = 2

    float *qp, *kp, *vp, *ap;
    cudaGetSymbolAddress((void**)&qp, g_q);
    cudaGetSymbolAddress((void**)&kp, g_k);
    cudaGetSymbolAddress((void**)&vp, g_v);
    cudaGetSymbolAddress((void**)&ap, g_attn);

    const size_t attn_smem = (size_t)(D_HEAD * BQ + D_HEAD * BKT + BKT * D_HEAD
                                      + BKT * PSTR + 3 * BQ) * sizeof(float);
    cudaFuncSetAttribute(attn_kernel, cudaFuncAttributeMaxDynamicSharedMemorySize,
                         (int)attn_smem);

    dim3 gdim(D_MODEL / GN, BT / GM);   // (16, 32)
    gemm_nt_bias<<<gdim, 256>>>(x, Wq, bq, qp, BT, D_MODEL, D_MODEL);
    gemm_nt_bias<<<gdim, 256>>>(x, Wk, bk, kp, BT, D_MODEL, D_MODEL);
    gemm_nt_bias<<<gdim, 256>>>(x, Wv, bv, vp, BT, D_MODEL, D_MODEL);

    rmsnorm_rope<<<BT, 256>>>(qp, qnw, cosb, sinb);
    rmsnorm_rope<<<BT, 256>>>(kp, knw, cosb, sinb);

    dim3 adim(T_SEQ / BQ, N_HEADS, Bb);  // (32, 16, 2)
    attn_kernel<<<adim, 256, attn_smem>>>(qp, kp, vp, ap);

    gemm_nt_bias<<<gdim, 256>>>(ap, Wo, bo, out, BT, D_MODEL, D_MODEL);
}

// round 4
// speedup vs baseline: 1.1106x; 1.1106x over previous
#include <cuda_runtime.h>
#include <cstdint>
#include <math.h>

#define D_MODEL 2048
#define T_SEQ   2048
#define N_HEADS 16
#define D_HEAD  128
#define BT_MAX  4096   // B=2 * T=2048

// ---------------- scratch (device globals; allocation-free) ----------------
__device__ float g_q[(size_t)BT_MAX * D_MODEL];
__device__ float g_k[(size_t)BT_MAX * D_MODEL];
__device__ float g_v[(size_t)BT_MAX * D_MODEL];
__device__ float g_attn[(size_t)BT_MAX * D_MODEL];

// ---------------- 3xTF32 mma.sync GEMM: C[M,N] = A[M,K] @ B[N,K]^T + bias ----------------
// CTA tile 128x128, K-tile 32 floats, 8 warps (2x4), warp tile 64x32.
#define TM 128
#define TN 128
#define TKF 32
#define LDS_STR 36                        // padded row stride (floats)
#define STAGE_F ((TM + TN) * LDS_STR)     // 9216 floats per stage
#define GSTAGES 3
#define GEMM_SMEM (GSTAGES * STAGE_F * 4) // 110592 bytes

__device__ __forceinline__ uint32_t smem_u32(const void* p) {
    uint32_t a;
    asm("{ .reg .u64 t; cvta.to.shared.u64 t, %1; cvt.u32.u64 %0, t; }" : "=r"(a) : "l"(p));
    return a;
}

__device__ __forceinline__ void mma_tf32(float* c, uint32_t a0, uint32_t a1,
                                         uint32_t a2, uint32_t a3,
                                         uint32_t b0, uint32_t b1) {
    asm volatile(
        "mma.sync.aligned.m16n8k8.row.col.f32.tf32.tf32.f32 "
        "{%0,%1,%2,%3}, {%4,%5,%6,%7}, {%8,%9}, {%0,%1,%2,%3};"
        : "+f"(c[0]), "+f"(c[1]), "+f"(c[2]), "+f"(c[3])
        : "r"(a0), "r"(a1), "r"(a2), "r"(a3), "r"(b0), "r"(b1));
}

// split x into tf32 hi + tf32 lo (3xTF32 decomposition)
__device__ __forceinline__ void tf32_split(float x, uint32_t& hi, uint32_t& lo) {
    asm("cvt.rna.tf32.f32 %0, %1;" : "=r"(hi) : "f"(x));
    float rem = x - __uint_as_float(hi);
    asm("cvt.rna.tf32.f32 %0, %1;" : "=r"(lo) : "f"(rem));
}

__global__ __launch_bounds__(256) void gemm_tc(
    const float* __restrict__ A,
    const float* __restrict__ B0, const float* __restrict__ bias0, float* __restrict__ C0,
    const float* __restrict__ B1, const float* __restrict__ bias1, float* __restrict__ C1,
    const float* __restrict__ B2, const float* __restrict__ bias2, float* __restrict__ C2,
    int M, int N, int K)
{
    extern __shared__ float smem[];
    const int tid = threadIdx.x;
    const int bz = blockIdx.z;
    const float* Bm  = (bz == 0) ? B0 : (bz == 1) ? B1 : B2;
    const float* bia = (bz == 0) ? bias0 : (bz == 1) ? bias1 : bias2;
    float*       C   = (bz == 0) ? C0 : (bz == 1) ? C1 : C2;

    const int m0 = blockIdx.y * TM;
    const int n0 = blockIdx.x * TN;
    const int NTILES = K / TKF;   // 64

    // ---- load mapping: 256 threads, 4 float4 for A + 4 for B per thread ----
    const int lr = tid >> 1;                 // 0..127 row
    const int lj0 = (tid & 1) * 4;           // float4 index base (0 or 4)
    const float* Ag = A  + (size_t)(m0 + lr) * K + lj0 * 4;
    const float* Bg = Bm + (size_t)(n0 + lr) * K + lj0 * 4;
    const uint32_t sA = smem_u32(smem) + (uint32_t)(lr * LDS_STR + lj0 * 4) * 4u;
    const uint32_t sB = sA + (uint32_t)(TM * LDS_STR) * 4u;

#define LOAD_TILE(t, s) do {                                                     \
        uint32_t _so = (uint32_t)((s) * STAGE_F) * 4u;                           \
        size_t _go = (size_t)(t) * TKF;                                          \
        _Pragma("unroll")                                                        \
        for (int _i = 0; _i < 4; _i++) {                                         \
            asm volatile("cp.async.cg.shared.global [%0], [%1], 16;"             \
                :: "r"(sA + _so + _i * 16u), "l"(Ag + _go + _i * 4));            \
            asm volatile("cp.async.cg.shared.global [%0], [%1], 16;"             \
                :: "r"(sB + _so + _i * 16u), "l"(Bg + _go + _i * 4));            \
        } } while (0)

    const int warp = tid >> 5, lane = tid & 31;
    const int wm = (warp >> 2) * 64, wn = (warp & 3) * 32;
    const int g = lane >> 2, tg = lane & 3;

    float c[4][4][4];
#pragma unroll
    for (int mi = 0; mi < 4; mi++)
#pragma unroll
        for (int ni = 0; ni < 4; ni++)
#pragma unroll
            for (int r = 0; r < 4; r++) c[mi][ni][r] = 0.f;

    // prologue
    LOAD_TILE(0, 0);
    asm volatile("cp.async.commit_group;" ::: "memory");
    LOAD_TILE(1, 1);
    asm volatile("cp.async.commit_group;" ::: "memory");

    const float* As_w = smem + (wm + g) * LDS_STR + tg;
    const float* Bs_w = smem + TM * LDS_STR + (wn + g) * LDS_STR + tg;

    for (int kt = 0; kt < NTILES; kt++) {
        asm volatile("cp.async.wait_group 1;" ::: "memory");
        __syncthreads();

        int lt = kt + 2;
        if (lt < NTILES) LOAD_TILE(lt, lt % GSTAGES);
        asm volatile("cp.async.commit_group;" ::: "memory");

        const float* As = As_w + (kt % GSTAGES) * STAGE_F;
        const float* Bs = Bs_w + (kt % GSTAGES) * STAGE_F;

#pragma unroll
        for (int ks = 0; ks < 4; ks++) {
            uint32_t ah[4][4], al[4][4], bh[4][2], bl[4][2];
#pragma unroll
            for (int mi = 0; mi < 4; mi++) {
                const float* ap = As + mi * 16 * LDS_STR + ks * 8;
                tf32_split(ap[0],                ah[mi][0], al[mi][0]);
                tf32_split(ap[8 * LDS_STR],      ah[mi][1], al[mi][1]);
                tf32_split(ap[4],                ah[mi][2], al[mi][2]);
                tf32_split(ap[8 * LDS_STR + 4],  ah[mi][3], al[mi][3]);
            }
#pragma unroll
            for (int ni = 0; ni < 4; ni++) {
                const float* bp = Bs + ni * 8 * LDS_STR + ks * 8;
                tf32_split(bp[0], bh[ni][0], bl[ni][0]);
                tf32_split(bp[4], bh[ni][1], bl[ni][1]);
            }
#pragma unroll
            for (int mi = 0; mi < 4; mi++)
#pragma unroll
                for (int ni = 0; ni < 4; ni++) {
                    // hi*lo + lo*hi first, hi*hi last (largest term added last)
                    mma_tf32(c[mi][ni], ah[mi][0], ah[mi][1], ah[mi][2], ah[mi][3],
                             bl[ni][0], bl[ni][1]);
                    mma_tf32(c[mi][ni], al[mi][0], al[mi][1], al[mi][2], al[mi][3],
                             bh[ni][0], bh[ni][1]);
                    mma_tf32(c[mi][ni], ah[mi][0], ah[mi][1], ah[mi][2], ah[mi][3],
                             bh[ni][0], bh[ni][1]);
                }
        }
    }

    // ---- epilogue: bias + store ----
#pragma unroll
    for (int ni = 0; ni < 4; ni++) {
        int col = n0 + wn + ni * 8 + 2 * tg;
        float2 bb = *(const float2*)(bia + col);
#pragma unroll
        for (int mi = 0; mi < 4; mi++) {
            int row = m0 + wm + mi * 16 + g;
            float2 o0, o1;
            o0.x = c[mi][ni][0] + bb.x; o0.y = c[mi][ni][1] + bb.y;
            o1.x = c[mi][ni][2] + bb.x; o1.y = c[mi][ni][3] + bb.y;
            *(float2*)(C + (size_t)row * N + col) = o0;
            *(float2*)(C + (size_t)(row + 8) * N + col) = o1;
        }
    }
#undef LOAD_TILE
}

// ---------------- fused RMSNorm (over D=2048) + interleaved RoPE ----------------
__global__ __launch_bounds__(256) void rmsnorm_rope(
    float* __restrict__ h, const float* __restrict__ w,
    const float* __restrict__ cosb, const float* __restrict__ sinb)
{
    const int row = blockIdx.x;
    const int t = row & (T_SEQ - 1);
    float* hp = h + (size_t)row * D_MODEL;
    const float* cp = cosb + (size_t)t * D_MODEL;
    const float* sp = sinb + (size_t)t * D_MODEL;
    const int tid = threadIdx.x;

    float4 vals[2];
    float ss = 0.f;
#pragma unroll
    for (int i = 0; i < 2; i++) {
        float4 v = ((const float4*)hp)[tid + i * 256];
        vals[i] = v;
        ss += v.x * v.x + v.y * v.y + v.z * v.z + v.w * v.w;
    }
#pragma unroll
    for (int o = 16; o > 0; o >>= 1) ss += __shfl_xor_sync(0xffffffffu, ss, o);
    __shared__ float red[8];
    __shared__ float s_inv;
    if ((tid & 31) == 0) red[tid >> 5] = ss;
    __syncthreads();
    if (tid == 0) {
        float tot = 0.f;
#pragma unroll
        for (int i = 0; i < 8; i++) tot += red[i];
        s_inv = rsqrtf(tot * (1.0f / D_MODEL) + 1e-6f);
    }
    __syncthreads();
    const float inv = s_inv;

#pragma unroll
    for (int i = 0; i < 2; i++) {
        int fi = tid + i * 256;
        float4 v = vals[i];
        float4 wv = ((const float4*)w)[fi];
        float4 c4 = ((const float4*)cp)[fi];
        float4 s4 = ((const float4*)sp)[fi];
        float nx = v.x * inv * wv.x;
        float ny = v.y * inv * wv.y;
        float nz = v.z * inv * wv.z;
        float nw = v.w * inv * wv.w;
        float4 o;
        o.x = nx * c4.x - ny * s4.x;
        o.y = ny * c4.y + nx * s4.y;
        o.z = nz * c4.z - nw * s4.z;
        o.w = nw * c4.w + nz * s4.w;
        ((float4*)hp)[fi] = o;
    }
}

// ---------------- flash attention (fp32, non-causal) ----------------
#define BQ  64
#define BKT 64
#define PSTR 68

__global__ __launch_bounds__(256) void attn_kernel(
    const float* __restrict__ Q, const float* __restrict__ Kg,
    const float* __restrict__ Vg, float* __restrict__ Og)
{
    extern __shared__ float smem[];
    float* Qs = smem;
    float* Ks = Qs + D_HEAD * BQ;
    float* Vs = Ks + D_HEAD * BKT;
    float* Ps = Vs + BKT * D_HEAD;
    float* m_s = Ps + BKT * PSTR;
    float* l_s = m_s + BQ;
    float* corr_s = l_s + BQ;

    const int tid = threadIdx.x;
    const int h = blockIdx.y, b = blockIdx.z;
    const int q0 = blockIdx.x * BQ;
    const size_t rowbase = (size_t)b * T_SEQ;
    const float scale = 0.08838834764831845f;

    const int r0 = (tid >> 4) * 4;
    const int c0 = (tid & 15) * 4;
    const int oc0 = (tid & 15) * 8;

#pragma unroll
    for (int i = 0; i < 8; i++) {
        int s = tid + i * 256;
        int d4 = s >> 6;
        int r = s & 63;
        float4 v = *(const float4*)(Q + (rowbase + q0 + r) * D_MODEL + h * D_HEAD + d4 * 4);
        Qs[(4 * d4 + 0) * BQ + r] = v.x * scale;
        Qs[(4 * d4 + 1) * BQ + r] = v.y * scale;
        Qs[(4 * d4 + 2) * BQ + r] = v.z * scale;
        Qs[(4 * d4 + 3) * BQ + r] = v.w * scale;
    }
    if (tid < BQ) { m_s[tid] = -1e30f; l_s[tid] = 0.f; }

    float Oacc[4][8];
#pragma unroll
    for (int i = 0; i < 4; i++)
#pragma unroll
        for (int j = 0; j < 8; j++) Oacc[i][j] = 0.f;

    for (int kt = 0; kt < T_SEQ; kt += BKT) {
        __syncthreads();

#pragma unroll
        for (int i = 0; i < 8; i++) {
            int s = tid + i * 256;
            int d4 = s >> 6;
            int cc = s & 63;
            float4 v = *(const float4*)(Kg + (rowbase + kt + cc) * D_MODEL + h * D_HEAD + d4 * 4);
            Ks[(4 * d4 + 0) * BKT + cc] = v.x;
            Ks[(4 * d4 + 1) * BKT + cc] = v.y;
            Ks[(4 * d4 + 2) * BKT + cc] = v.z;
            Ks[(4 * d4 + 3) * BKT + cc] = v.w;
        }
#pragma unroll
        for (int i = 0; i < 8; i++) {
            int s = tid + i * 256;
            int kk = s >> 5;
            int d4 = s & 31;
            float4 v = *(const float4*)(Vg + (rowbase + kt + kk) * D_MODEL + h * D_HEAD + d4 * 4);
            *(float4*)&Vs[kk * D_HEAD + d4 * 4] = v;
        }
        __syncthreads();

        float Sacc[4][4];
#pragma unroll
        for (int i = 0; i < 4; i++)
#pragma unroll
            for (int j = 0; j < 4; j++) Sacc[i][j] = 0.f;

#pragma unroll 4
        for (int d = 0; d < D_HEAD; d++) {
            float4 qa = *(const float4*)&Qs[d * BQ + r0];
            float4 kb = *(const float4*)&Ks[d * BKT + c0];
            float a[4] = {qa.x, qa.y, qa.z, qa.w};
            float bb[4] = {kb.x, kb.y, kb.z, kb.w};
#pragma unroll
            for (int i = 0; i < 4; i++)
#pragma unroll
                for (int j = 0; j < 4; j++)
                    Sacc[i][j] += a[i] * bb[j];
        }
#pragma unroll
        for (int j = 0; j < 4; j++) {
            float4 col = make_float4(Sacc[0][j], Sacc[1][j], Sacc[2][j], Sacc[3][j]);
            *(float4*)&Ps[(c0 + j) * PSTR + r0] = col;
        }
        __syncthreads();

        if (tid < BQ) {
            int r = tid;
            float m_old = m_s[r];
            float mx = m_old;
#pragma unroll 8
            for (int cc = 0; cc < BKT; cc++) mx = fmaxf(mx, Ps[cc * PSTR + r]);
            float corr = __expf(m_old - mx);
            float sum = 0.f;
#pragma unroll 8
            for (int cc = 0; cc < BKT; cc++) {
                float p = __expf(Ps[cc * PSTR + r] - mx);
                Ps[cc * PSTR + r] = p;
                sum += p;
            }
            l_s[r] = l_s[r] * corr + sum;
            m_s[r] = mx;
            corr_s[r] = corr;
        }
        __syncthreads();

#pragma unroll
        for (int i = 0; i < 4; i++) {
            float corr = corr_s[r0 + i];
#pragma unroll
            for (int j = 0; j < 8; j++) Oacc[i][j] *= corr;
        }
#pragma unroll 2
        for (int kk = 0; kk < BKT; kk++) {
            float4 p4 = *(const float4*)&Ps[kk * PSTR + r0];
            float4 va = *(const float4*)&Vs[kk * D_HEAD + oc0];
            float4 vb = *(const float4*)&Vs[kk * D_HEAD + oc0 + 4];
            float p[4] = {p4.x, p4.y, p4.z, p4.w};
            float vv[8] = {va.x, va.y, va.z, va.w, vb.x, vb.y, vb.z, vb.w};
#pragma unroll
            for (int i = 0; i < 4; i++)
#pragma unroll
                for (int j = 0; j < 8; j++)
                    Oacc[i][j] += p[i] * vv[j];
        }
    }

    __syncthreads();
#pragma unroll
    for (int i = 0; i < 4; i++) {
        float linv = 1.0f / l_s[r0 + i];
        float* Op = Og + (rowbase + q0 + r0 + i) * D_MODEL + h * D_HEAD + oc0;
        float4 o0, o1;
        o0.x = Oacc[i][0] * linv; o0.y = Oacc[i][1] * linv;
        o0.z = Oacc[i][2] * linv; o0.w = Oacc[i][3] * linv;
        o1.x = Oacc[i][4] * linv; o1.y = Oacc[i][5] * linv;
        o1.z = Oacc[i][6] * linv; o1.w = Oacc[i][7] * linv;
        *(float4*)(Op) = o0;
        *(float4*)(Op + 4) = o1;
    }
}

// ---------------- host launch ----------------
extern "C" void kernel_launch(void* const* d_in, const int* in_sizes, int n_in,
                              void* d_out, int out_size)
{
    const float* x   = (const float*)d_in[0];
    const float* cosb= (const float*)d_in[1];
    const float* sinb= (const float*)d_in[2];
    const float* Wq  = (const float*)d_in[3];
    const float* bq  = (const float*)d_in[4];
    const float* Wk  = (const float*)d_in[5];
    const float* bk  = (const float*)d_in[6];
    const float* Wv  = (const float*)d_in[7];
    const float* bv  = (const float*)d_in[8];
    const float* qnw = (const float*)d_in[9];
    const float* knw = (const float*)d_in[10];
    const float* Wo  = (const float*)d_in[11];
    const float* bo  = (const float*)d_in[12];
    float* out = (float*)d_out;

    const int BT = in_sizes[0] / D_MODEL;    // 4096
    const int Bb = BT / T_SEQ;               // 2

    float *qp, *kp, *vp, *ap;
    cudaGetSymbolAddress((void**)&qp, g_q);
    cudaGetSymbolAddress((void**)&kp, g_k);
    cudaGetSymbolAddress((void**)&vp, g_v);
    cudaGetSymbolAddress((void**)&ap, g_attn);

    cudaFuncSetAttribute(gemm_tc, cudaFuncAttributeMaxDynamicSharedMemorySize, GEMM_SMEM);
    const size_t attn_smem = (size_t)(D_HEAD * BQ + D_HEAD * BKT + BKT * D_HEAD
                                      + BKT * PSTR + 3 * BQ) * sizeof(float);
    cudaFuncSetAttribute(attn_kernel, cudaFuncAttributeMaxDynamicSharedMemorySize,
                         (int)attn_smem);

    // fused QKV: grid.z selects the weight/bias/output triple
    dim3 gq(D_MODEL / TN, BT / TM, 3);
    gemm_tc<<<gq, 256, GEMM_SMEM>>>(x, Wq, bq, qp, Wk, bk, kp, Wv, bv, vp,
                                    BT, D_MODEL, D_MODEL);

    rmsnorm_rope<<<BT, 256>>>(qp, qnw, cosb, sinb);
    rmsnorm_rope<<<BT, 256>>>(kp, knw, cosb, sinb);

    dim3 adim(T_SEQ / BQ, N_HEADS, Bb);
    attn_kernel<<<adim, 256, attn_smem>>>(qp, kp, vp, ap);

    dim3 go(D_MODEL / TN, BT / TM, 1);
    gemm_tc<<<go, 256, GEMM_SMEM>>>(ap, Wo, bo, out, Wo, bo, out, Wo, bo, out,
                                    BT, D_MODEL, D_MODEL);
}

// round 5
// speedup vs baseline: 1.3961x; 1.2570x over previous
#include <cuda_runtime.h>
#include <cuda_bf16.h>
#include <cstdint>
#include <math.h>

#define D_MODEL 2048
#define T_SEQ   2048
#define N_HEADS 16
#define D_HEAD  128
#define BT_MAX  4096   // B=2 * T=2048

// ---------------- scratch (device globals; allocation-free) ----------------
__device__ float g_q[(size_t)BT_MAX * D_MODEL];
__device__ float g_k[(size_t)BT_MAX * D_MODEL];
__device__ float g_v[(size_t)BT_MAX * D_MODEL];
__device__ float g_attn[(size_t)BT_MAX * D_MODEL];

__device__ __nv_bfloat16 g_xh[(size_t)BT_MAX * D_MODEL];
__device__ __nv_bfloat16 g_xl[(size_t)BT_MAX * D_MODEL];
__device__ __nv_bfloat16 g_wh[(size_t)4 * D_MODEL * D_MODEL];  // Wq,Wk,Wv,Wo hi
__device__ __nv_bfloat16 g_wl[(size_t)4 * D_MODEL * D_MODEL];  // lo
__device__ __nv_bfloat16 g_ah[(size_t)BT_MAX * D_MODEL];       // attn out hi
__device__ __nv_bfloat16 g_al[(size_t)BT_MAX * D_MODEL];

// ---------------- split fp32 -> bf16 hi + bf16 lo ----------------
__global__ __launch_bounds__(256) void split_bf16(
    const float* __restrict__ src, __nv_bfloat16* __restrict__ hi,
    __nv_bfloat16* __restrict__ lo, int n4)
{
    int i = blockIdx.x * 256 + threadIdx.x;
    if (i >= n4) return;
    float4 v = ((const float4*)src)[i];
    __nv_bfloat16 h0 = __float2bfloat16(v.x);
    __nv_bfloat16 h1 = __float2bfloat16(v.y);
    __nv_bfloat16 h2 = __float2bfloat16(v.z);
    __nv_bfloat16 h3 = __float2bfloat16(v.w);
    __nv_bfloat16 l0 = __float2bfloat16(v.x - __bfloat162float(h0));
    __nv_bfloat16 l1 = __float2bfloat16(v.y - __bfloat162float(h1));
    __nv_bfloat16 l2 = __float2bfloat16(v.z - __bfloat162float(h2));
    __nv_bfloat16 l3 = __float2bfloat16(v.w - __bfloat162float(h3));
    __nv_bfloat162* hp = (__nv_bfloat162*)(hi + (size_t)i * 4);
    __nv_bfloat162* lp = (__nv_bfloat162*)(lo + (size_t)i * 4);
    hp[0] = __nv_bfloat162(h0, h1); hp[1] = __nv_bfloat162(h2, h3);
    lp[0] = __nv_bfloat162(l0, l1); lp[1] = __nv_bfloat162(l2, l3);
}

// ---------------- 3xBF16 mma.sync GEMM: C[M,N] = A[M,K] @ B[N,K]^T + bias ----------------
// CTA tile 128x128, K-tile 32, 8 warps (2x4), warp tile 64x32.
#define TM 128
#define TN 128
#define TKF 32
#define BSTR 40                               // bf16 row stride (elems)
#define REGION (TM * BSTR)                    // 5120 bf16 per region
#define STAGE_E (4 * REGION)                  // Ah, Al, Bh, Bl
#define GSTAGES 3
#define GEMM_SMEM (GSTAGES * STAGE_E * 2)     // 122880 bytes

__device__ __forceinline__ uint32_t smem_u32(const void* p) {
    uint32_t a;
    asm("{ .reg .u64 t; cvta.to.shared.u64 t, %1; cvt.u32.u64 %0, t; }" : "=r"(a) : "l"(p));
    return a;
}

__device__ __forceinline__ void mma_bf16(float* c, uint32_t a0, uint32_t a1,
                                         uint32_t a2, uint32_t a3,
                                         uint32_t b0, uint32_t b1) {
    asm volatile(
        "mma.sync.aligned.m16n8k16.row.col.f32.bf16.bf16.f32 "
        "{%0,%1,%2,%3}, {%4,%5,%6,%7}, {%8,%9}, {%0,%1,%2,%3};"
        : "+f"(c[0]), "+f"(c[1]), "+f"(c[2]), "+f"(c[3])
        : "r"(a0), "r"(a1), "r"(a2), "r"(a3), "r"(b0), "r"(b1));
}

__global__ __launch_bounds__(256) void gemm_bf16(
    const __nv_bfloat16* __restrict__ Ah, const __nv_bfloat16* __restrict__ Al,
    const __nv_bfloat16* __restrict__ Wh, const __nv_bfloat16* __restrict__ Wl,
    const float* __restrict__ bias0, float* __restrict__ C0,
    const float* __restrict__ bias1, float* __restrict__ C1,
    const float* __restrict__ bias2, float* __restrict__ C2,
    int M, int N, int K)
{
    extern __shared__ __nv_bfloat16 smem[];
    const int tid = threadIdx.x;
    const int bz = blockIdx.z;
    const __nv_bfloat16* Bh = Wh + (size_t)bz * D_MODEL * D_MODEL;
    const __nv_bfloat16* Bl = Wl + (size_t)bz * D_MODEL * D_MODEL;
    const float* bia = (bz == 0) ? bias0 : (bz == 1) ? bias1 : bias2;
    float*       C   = (bz == 0) ? C0 : (bz == 1) ? C1 : C2;

    const int m0 = blockIdx.y * TM;
    const int n0 = blockIdx.x * TN;
    const int NTILES = K / TKF;   // 64

    // ---- load mapping: 256 threads; row = tid>>1 (0..127), half = tid&1 ----
    const int lrow = tid >> 1;
    const int lhalf = tid & 1;
    const __nv_bfloat16* gAh = Ah + (size_t)(m0 + lrow) * K + lhalf * 16;
    const __nv_bfloat16* gAl = Al + (size_t)(m0 + lrow) * K + lhalf * 16;
    const __nv_bfloat16* gBh = Bh + (size_t)(n0 + lrow) * K + lhalf * 16;
    const __nv_bfloat16* gBl = Bl + (size_t)(n0 + lrow) * K + lhalf * 16;
    const uint32_t sbase = smem_u32(smem);
    const uint32_t sAh = sbase + (uint32_t)(lrow * BSTR + lhalf * 16) * 2u;
    const uint32_t sAl = sAh + REGION * 2u;
    const uint32_t sBh = sAh + 2u * REGION * 2u;
    const uint32_t sBl = sAh + 3u * REGION * 2u;

#define LOAD_TILE(t, s) do {                                                     \
        uint32_t _so = (uint32_t)((s) * STAGE_E) * 2u;                           \
        size_t _go = (size_t)(t) * TKF;                                          \
        _Pragma("unroll")                                                        \
        for (int _c = 0; _c < 2; _c++) {                                         \
            asm volatile("cp.async.cg.shared.global [%0], [%1], 16;"             \
                :: "r"(sAh + _so + _c * 16u), "l"(gAh + _go + _c * 8));          \
            asm volatile("cp.async.cg.shared.global [%0], [%1], 16;"             \
                :: "r"(sAl + _so + _c * 16u), "l"(gAl + _go + _c * 8));          \
            asm volatile("cp.async.cg.shared.global [%0], [%1], 16;"             \
                :: "r"(sBh + _so + _c * 16u), "l"(gBh + _go + _c * 8));          \
            asm volatile("cp.async.cg.shared.global [%0], [%1], 16;"             \
                :: "r"(sBl + _so + _c * 16u), "l"(gBl + _go + _c * 8));          \
        } } while (0)

    const int warp = tid >> 5, lane = tid & 31;
    const int wm = (warp >> 2) * 64, wn = (warp & 3) * 32;
    const int g = lane >> 2, tg = lane & 3;

    float c[4][4][4];
#pragma unroll
    for (int mi = 0; mi < 4; mi++)
#pragma unroll
        for (int ni = 0; ni < 4; ni++)
#pragma unroll
            for (int r = 0; r < 4; r++) c[mi][ni][r] = 0.f;

    // prologue
    LOAD_TILE(0, 0);
    asm volatile("cp.async.commit_group;" ::: "memory");
    LOAD_TILE(1, 1);
    asm volatile("cp.async.commit_group;" ::: "memory");

    // compute-side smem element bases (within region, per thread)
    const int aoff = (wm + g) * BSTR + 2 * tg;          // + mi*16*BSTR (+8*BSTR), +k
    const int boff = (wn + g) * BSTR + 2 * tg;          // + ni*8*BSTR, +k

    for (int kt = 0; kt < NTILES; kt++) {
        asm volatile("cp.async.wait_group 1;" ::: "memory");
        __syncthreads();

        int lt = kt + 2;
        if (lt < NTILES) LOAD_TILE(lt, lt % GSTAGES);
        asm volatile("cp.async.commit_group;" ::: "memory");

        const __nv_bfloat16* st = smem + (kt % GSTAGES) * STAGE_E;
        const __nv_bfloat16* pAh = st + aoff;
        const __nv_bfloat16* pAl = pAh + REGION;
        const __nv_bfloat16* pBh = st + 2 * REGION + boff;
        const __nv_bfloat16* pBl = pBh + REGION;

#pragma unroll
        for (int ks = 0; ks < 2; ks++) {
            const int kb = ks * 16;
            uint32_t ah[4][4], al[4][4], bh[4][2], bl[4][2];
#pragma unroll
            for (int mi = 0; mi < 4; mi++) {
                const int r1 = mi * 16 * BSTR + kb;
                const int r2 = r1 + 8 * BSTR;
                ah[mi][0] = *(const uint32_t*)(pAh + r1);
                ah[mi][1] = *(const uint32_t*)(pAh + r2);
                ah[mi][2] = *(const uint32_t*)(pAh + r1 + 8);
                ah[mi][3] = *(const uint32_t*)(pAh + r2 + 8);
                al[mi][0] = *(const uint32_t*)(pAl + r1);
                al[mi][1] = *(const uint32_t*)(pAl + r2);
                al[mi][2] = *(const uint32_t*)(pAl + r1 + 8);
                al[mi][3] = *(const uint32_t*)(pAl + r2 + 8);
            }
#pragma unroll
            for (int ni = 0; ni < 4; ni++) {
                const int rb = ni * 8 * BSTR + kb;
                bh[ni][0] = *(const uint32_t*)(pBh + rb);
                bh[ni][1] = *(const uint32_t*)(pBh + rb + 8);
                bl[ni][0] = *(const uint32_t*)(pBl + rb);
                bl[ni][1] = *(const uint32_t*)(pBl + rb + 8);
            }
#pragma unroll
            for (int mi = 0; mi < 4; mi++)
#pragma unroll
                for (int ni = 0; ni < 4; ni++) {
                    mma_bf16(c[mi][ni], ah[mi][0], ah[mi][1], ah[mi][2], ah[mi][3],
                             bl[ni][0], bl[ni][1]);
                    mma_bf16(c[mi][ni], al[mi][0], al[mi][1], al[mi][2], al[mi][3],
                             bh[ni][0], bh[ni][1]);
                    mma_bf16(c[mi][ni], ah[mi][0], ah[mi][1], ah[mi][2], ah[mi][3],
                             bh[ni][0], bh[ni][1]);
                }
        }
    }

    // ---- epilogue: bias + store ----
#pragma unroll
    for (int ni = 0; ni < 4; ni++) {
        int col = n0 + wn + ni * 8 + 2 * tg;
        float2 bb = *(const float2*)(bia + col);
#pragma unroll
        for (int mi = 0; mi < 4; mi++) {
            int row = m0 + wm + mi * 16 + g;
            float2 o0, o1;
            o0.x = c[mi][ni][0] + bb.x; o0.y = c[mi][ni][1] + bb.y;
            o1.x = c[mi][ni][2] + bb.x; o1.y = c[mi][ni][3] + bb.y;
            *(float2*)(C + (size_t)row * N + col) = o0;
            *(float2*)(C + (size_t)(row + 8) * N + col) = o1;
        }
    }
#undef LOAD_TILE
}

// ---------------- fused RMSNorm (over D=2048) + interleaved RoPE ----------------
__global__ __launch_bounds__(256) void rmsnorm_rope(
    float* __restrict__ h, const float* __restrict__ w,
    const float* __restrict__ cosb, const float* __restrict__ sinb)
{
    const int row = blockIdx.x;
    const int t = row & (T_SEQ - 1);
    float* hp = h + (size_t)row * D_MODEL;
    const float* cp = cosb + (size_t)t * D_MODEL;
    const float* sp = sinb + (size_t)t * D_MODEL;
    const int tid = threadIdx.x;

    float4 vals[2];
    float ss = 0.f;
#pragma unroll
    for (int i = 0; i < 2; i++) {
        float4 v = ((const float4*)hp)[tid + i * 256];
        vals[i] = v;
        ss += v.x * v.x + v.y * v.y + v.z * v.z + v.w * v.w;
    }
#pragma unroll
    for (int o = 16; o > 0; o >>= 1) ss += __shfl_xor_sync(0xffffffffu, ss, o);
    __shared__ float red[8];
    __shared__ float s_inv;
    if ((tid & 31) == 0) red[tid >> 5] = ss;
    __syncthreads();
    if (tid == 0) {
        float tot = 0.f;
#pragma unroll
        for (int i = 0; i < 8; i++) tot += red[i];
        s_inv = rsqrtf(tot * (1.0f / D_MODEL) + 1e-6f);
    }
    __syncthreads();
    const float inv = s_inv;

#pragma unroll
    for (int i = 0; i < 2; i++) {
        int fi = tid + i * 256;
        float4 v = vals[i];
        float4 wv = ((const float4*)w)[fi];
        float4 c4 = ((const float4*)cp)[fi];
        float4 s4 = ((const float4*)sp)[fi];
        float nx = v.x * inv * wv.x;
        float ny = v.y * inv * wv.y;
        float nz = v.z * inv * wv.z;
        float nw = v.w * inv * wv.w;
        float4 o;
        o.x = nx * c4.x - ny * s4.x;
        o.y = ny * c4.y + nx * s4.y;
        o.z = nz * c4.z - nw * s4.z;
        o.w = nw * c4.w + nz * s4.w;
        ((float4*)hp)[fi] = o;
    }
}

// ---------------- flash attention (fp32, non-causal) ----------------
#define BQ  64
#define BKT 64
#define PSTR 68

__global__ __launch_bounds__(256) void attn_kernel(
    const float* __restrict__ Q, const float* __restrict__ Kg,
    const float* __restrict__ Vg, float* __restrict__ Og)
{
    extern __shared__ float smemf[];
    float* Qs = smemf;
    float* Ks = Qs + D_HEAD * BQ;
    float* Vs = Ks + D_HEAD * BKT;
    float* Ps = Vs + BKT * D_HEAD;
    float* m_s = Ps + BKT * PSTR;
    float* l_s = m_s + BQ;
    float* corr_s = l_s + BQ;

    const int tid = threadIdx.x;
    const int h = blockIdx.y, b = blockIdx.z;
    const int q0 = blockIdx.x * BQ;
    const size_t rowbase = (size_t)b * T_SEQ;
    const float scale = 0.08838834764831845f;

    const int r0 = (tid >> 4) * 4;
    const int c0 = (tid & 15) * 4;
    const int oc0 = (tid & 15) * 8;

#pragma unroll
    for (int i = 0; i < 8; i++) {
        int s = tid + i * 256;
        int d4 = s >> 6;
        int r = s & 63;
        float4 v = *(const float4*)(Q + (rowbase + q0 + r) * D_MODEL + h * D_HEAD + d4 * 4);
        Qs[(4 * d4 + 0) * BQ + r] = v.x * scale;
        Qs[(4 * d4 + 1) * BQ + r] = v.y * scale;
        Qs[(4 * d4 + 2) * BQ + r] = v.z * scale;
        Qs[(4 * d4 + 3) * BQ + r] = v.w * scale;
    }
    if (tid < BQ) { m_s[tid] = -1e30f; l_s[tid] = 0.f; }

    float Oacc[4][8];
#pragma unroll
    for (int i = 0; i < 4; i++)
#pragma unroll
        for (int j = 0; j < 8; j++) Oacc[i][j] = 0.f;

    for (int kt = 0; kt < T_SEQ; kt += BKT) {
        __syncthreads();

#pragma unroll
        for (int i = 0; i < 8; i++) {
            int s = tid + i * 256;
            int d4 = s >> 6;
            int cc = s & 63;
            float4 v = *(const float4*)(Kg + (rowbase + kt + cc) * D_MODEL + h * D_HEAD + d4 * 4);
            Ks[(4 * d4 + 0) * BKT + cc] = v.x;
            Ks[(4 * d4 + 1) * BKT + cc] = v.y;
            Ks[(4 * d4 + 2) * BKT + cc] = v.z;
            Ks[(4 * d4 + 3) * BKT + cc] = v.w;
        }
#pragma unroll
        for (int i = 0; i < 8; i++) {
            int s = tid + i * 256;
            int kk = s >> 5;
            int d4 = s & 31;
            float4 v = *(const float4*)(Vg + (rowbase + kt + kk) * D_MODEL + h * D_HEAD + d4 * 4);
            *(float4*)&Vs[kk * D_HEAD + d4 * 4] = v;
        }
        __syncthreads();

        float Sacc[4][4];
#pragma unroll
        for (int i = 0; i < 4; i++)
#pragma unroll
            for (int j = 0; j < 4; j++) Sacc[i][j] = 0.f;

#pragma unroll 4
        for (int d = 0; d < D_HEAD; d++) {
            float4 qa = *(const float4*)&Qs[d * BQ + r0];
            float4 kb = *(const float4*)&Ks[d * BKT + c0];
            float a[4] = {qa.x, qa.y, qa.z, qa.w};
            float bb[4] = {kb.x, kb.y, kb.z, kb.w};
#pragma unroll
            for (int i = 0; i < 4; i++)
#pragma unroll
                for (int j = 0; j < 4; j++)
                    Sacc[i][j] += a[i] * bb[j];
        }
#pragma unroll
        for (int j = 0; j < 4; j++) {
            float4 col = make_float4(Sacc[0][j], Sacc[1][j], Sacc[2][j], Sacc[3][j]);
            *(float4*)&Ps[(c0 + j) * PSTR + r0] = col;
        }
        __syncthreads();

        if (tid < BQ) {
            int r = tid;
            float m_old = m_s[r];
            float mx = m_old;
#pragma unroll 8
            for (int cc = 0; cc < BKT; cc++) mx = fmaxf(mx, Ps[cc * PSTR + r]);
            float corr = __expf(m_old - mx);
            float sum = 0.f;
#pragma unroll 8
            for (int cc = 0; cc < BKT; cc++) {
                float p = __expf(Ps[cc * PSTR + r] - mx);
                Ps[cc * PSTR + r] = p;
                sum += p;
            }
            l_s[r] = l_s[r] * corr + sum;
            m_s[r] = mx;
            corr_s[r] = corr;
        }
        __syncthreads();

#pragma unroll
        for (int i = 0; i < 4; i++) {
            float corr = corr_s[r0 + i];
#pragma unroll
            for (int j = 0; j < 8; j++) Oacc[i][j] *= corr;
        }
#pragma unroll 2
        for (int kk = 0; kk < BKT; kk++) {
            float4 p4 = *(const float4*)&Ps[kk * PSTR + r0];
            float4 va = *(const float4*)&Vs[kk * D_HEAD + oc0];
            float4 vb = *(const float4*)&Vs[kk * D_HEAD + oc0 + 4];
            float p[4] = {p4.x, p4.y, p4.z, p4.w};
            float vv[8] = {va.x, va.y, va.z, va.w, vb.x, vb.y, vb.z, vb.w};
#pragma unroll
            for (int i = 0; i < 4; i++)
#pragma unroll
                for (int j = 0; j < 8; j++)
                    Oacc[i][j] += p[i] * vv[j];
        }
    }

    __syncthreads();
#pragma unroll
    for (int i = 0; i < 4; i++) {
        float linv = 1.0f / l_s[r0 + i];
        float* Op = Og + (rowbase + q0 + r0 + i) * D_MODEL + h * D_HEAD + oc0;
        float4 o0, o1;
        o0.x = Oacc[i][0] * linv; o0.y = Oacc[i][1] * linv;
        o0.z = Oacc[i][2] * linv; o0.w = Oacc[i][3] * linv;
        o1.x = Oacc[i][4] * linv; o1.y = Oacc[i][5] * linv;
        o1.z = Oacc[i][6] * linv; o1.w = Oacc[i][7] * linv;
        *(float4*)(Op) = o0;
        *(float4*)(Op + 4) = o1;
    }
}

// ---------------- host launch ----------------
extern "C" void kernel_launch(void* const* d_in, const int* in_sizes, int n_in,
                              void* d_out, int out_size)
{
    const float* x   = (const float*)d_in[0];
    const float* cosb= (const float*)d_in[1];
    const float* sinb= (const float*)d_in[2];
    const float* Wq  = (const float*)d_in[3];
    const float* bq  = (const float*)d_in[4];
    const float* Wk  = (const float*)d_in[5];
    const float* bk  = (const float*)d_in[6];
    const float* Wv  = (const float*)d_in[7];
    const float* bv  = (const float*)d_in[8];
    const float* qnw = (const float*)d_in[9];
    const float* knw = (const float*)d_in[10];
    const float* Wo  = (const float*)d_in[11];
    const float* bo  = (const float*)d_in[12];
    float* out = (float*)d_out;

    const int BT = in_sizes[0] / D_MODEL;    // 4096
    const int Bb = BT / T_SEQ;               // 2

    float *qp, *kp, *vp, *ap;
    cudaGetSymbolAddress((void**)&qp, g_q);
    cudaGetSymbolAddress((void**)&kp, g_k);
    cudaGetSymbolAddress((void**)&vp, g_v);
    cudaGetSymbolAddress((void**)&ap, g_attn);
    __nv_bfloat16 *xh, *xl, *wh, *wl, *ah, *al;
    cudaGetSymbolAddress((void**)&xh, g_xh);
    cudaGetSymbolAddress((void**)&xl, g_xl);
    cudaGetSymbolAddress((void**)&wh, g_wh);
    cudaGetSymbolAddress((void**)&wl, g_wl);
    cudaGetSymbolAddress((void**)&ah, g_ah);
    cudaGetSymbolAddress((void**)&al, g_al);

    cudaFuncSetAttribute(gemm_bf16, cudaFuncAttributeMaxDynamicSharedMemorySize, GEMM_SMEM);
    const size_t attn_smem = (size_t)(D_HEAD * BQ + D_HEAD * BKT + BKT * D_HEAD
                                      + BKT * PSTR + 3 * BQ) * sizeof(float);
    cudaFuncSetAttribute(attn_kernel, cudaFuncAttributeMaxDynamicSharedMemorySize,
                         (int)attn_smem);

    const int nX4 = BT * D_MODEL / 4;               // 2M float4
    const int nW4 = D_MODEL * D_MODEL / 4;          // 1M float4
    const size_t woff = (size_t)D_MODEL * D_MODEL;

    // split inputs to bf16 hi/lo
    split_bf16<<<(nX4 + 255) / 256, 256>>>(x, xh, xl, nX4);
    split_bf16<<<(nW4 + 255) / 256, 256>>>(Wq, wh + 0 * woff, wl + 0 * woff, nW4);
    split_bf16<<<(nW4 + 255) / 256, 256>>>(Wk, wh + 1 * woff, wl + 1 * woff, nW4);
    split_bf16<<<(nW4 + 255) / 256, 256>>>(Wv, wh + 2 * woff, wl + 2 * woff, nW4);
    split_bf16<<<(nW4 + 255) / 256, 256>>>(Wo, wh + 3 * woff, wl + 3 * woff, nW4);

    // fused QKV: grid.z selects weight/bias/output triple
    dim3 gq(D_MODEL / TN, BT / TM, 3);
    gemm_bf16<<<gq, 256, GEMM_SMEM>>>(xh, xl, wh, wl,
                                      bq, qp, bk, kp, bv, vp,
                                      BT, D_MODEL, D_MODEL);

    rmsnorm_rope<<<BT, 256>>>(qp, qnw, cosb, sinb);
    rmsnorm_rope<<<BT, 256>>>(kp, knw, cosb, sinb);

    dim3 adim(T_SEQ / BQ, N_HEADS, Bb);
    attn_kernel<<<adim, 256, attn_smem>>>(qp, kp, vp, ap);

    // split attention output, then O projection (weight index 3)
    split_bf16<<<(nX4 + 255) / 256, 256>>>(ap, ah, al, nX4);
    dim3 go(D_MODEL / TN, BT / TM, 1);
    gemm_bf16<<<go, 256, GEMM_SMEM>>>(ah, al, wh + 3 * woff, wl + 3 * woff,
                                      bo, out, bo, out, bo, out,
                                      BT, D_MODEL, D_MODEL);
}

// round 6
// speedup vs baseline: 2.8596x; 2.0484x over previous
#include <cuda_runtime.h>
#include <cuda_bf16.h>
#include <cstdint>
#include <math.h>

#define D_MODEL 2048
#define T_SEQ   2048
#define N_HEADS 16
#define D_HEAD  128
#define BT_MAX  4096   // B=2 * T=2048

// ---------------- scratch (device globals; allocation-free) ----------------
__device__ float g_q[(size_t)BT_MAX * D_MODEL];
__device__ float g_k[(size_t)BT_MAX * D_MODEL];
__device__ float g_v[(size_t)BT_MAX * D_MODEL];
__device__ float g_attn[(size_t)BT_MAX * D_MODEL];

__device__ __nv_bfloat16 g_xh[(size_t)BT_MAX * D_MODEL];
__device__ __nv_bfloat16 g_xl[(size_t)BT_MAX * D_MODEL];
__device__ __nv_bfloat16 g_wh[(size_t)4 * D_MODEL * D_MODEL];  // Wq,Wk,Wv,Wo hi
__device__ __nv_bfloat16 g_wl[(size_t)4 * D_MODEL * D_MODEL];  // lo
__device__ __nv_bfloat16 g_ah[(size_t)BT_MAX * D_MODEL];       // attn out hi
__device__ __nv_bfloat16 g_al[(size_t)BT_MAX * D_MODEL];

__device__ __nv_bfloat16 g_qh[(size_t)BT_MAX * D_MODEL];       // Q hi (scaled)
__device__ __nv_bfloat16 g_ql[(size_t)BT_MAX * D_MODEL];
__device__ __nv_bfloat16 g_kh[(size_t)BT_MAX * D_MODEL];       // K hi
__device__ __nv_bfloat16 g_kl[(size_t)BT_MAX * D_MODEL];
__device__ __nv_bfloat16 g_vth[(size_t)BT_MAX * D_MODEL];      // V^T hi [b,h,d,t]
__device__ __nv_bfloat16 g_vtl[(size_t)BT_MAX * D_MODEL];

__device__ __forceinline__ uint32_t smem_u32(const void* p) {
    uint32_t a;
    asm("{ .reg .u64 t; cvta.to.shared.u64 t, %1; cvt.u32.u64 %0, t; }" : "=r"(a) : "l"(p));
    return a;
}

__device__ __forceinline__ void mma_bf16(float* c, uint32_t a0, uint32_t a1,
                                         uint32_t a2, uint32_t a3,
                                         uint32_t b0, uint32_t b1) {
    asm volatile(
        "mma.sync.aligned.m16n8k16.row.col.f32.bf16.bf16.f32 "
        "{%0,%1,%2,%3}, {%4,%5,%6,%7}, {%8,%9}, {%0,%1,%2,%3};"
        : "+f"(c[0]), "+f"(c[1]), "+f"(c[2]), "+f"(c[3])
        : "r"(a0), "r"(a1), "r"(a2), "r"(a3), "r"(b0), "r"(b1));
}

__device__ __forceinline__ float ex2f(float x) {
    float r;
    asm("ex2.approx.f32 %0, %1;" : "=f"(r) : "f"(x));
    return r;
}

// ---------------- split fp32 -> bf16 hi + bf16 lo ----------------
__global__ __launch_bounds__(256) void split_bf16(
    const float* __restrict__ src, __nv_bfloat16* __restrict__ hi,
    __nv_bfloat16* __restrict__ lo, int n4)
{
    int i = blockIdx.x * 256 + threadIdx.x;
    if (i >= n4) return;
    float4 v = ((const float4*)src)[i];
    __nv_bfloat16 h0 = __float2bfloat16(v.x);
    __nv_bfloat16 h1 = __float2bfloat16(v.y);
    __nv_bfloat16 h2 = __float2bfloat16(v.z);
    __nv_bfloat16 h3 = __float2bfloat16(v.w);
    __nv_bfloat16 l0 = __float2bfloat16(v.x - __bfloat162float(h0));
    __nv_bfloat16 l1 = __float2bfloat16(v.y - __bfloat162float(h1));
    __nv_bfloat16 l2 = __float2bfloat16(v.z - __bfloat162float(h2));
    __nv_bfloat16 l3 = __float2bfloat16(v.w - __bfloat162float(h3));
    __nv_bfloat162* hp = (__nv_bfloat162*)(hi + (size_t)i * 4);
    __nv_bfloat162* lp = (__nv_bfloat162*)(lo + (size_t)i * 4);
    hp[0] = __nv_bfloat162(h0, h1); hp[1] = __nv_bfloat162(h2, h3);
    lp[0] = __nv_bfloat162(l0, l1); lp[1] = __nv_bfloat162(l2, l3);
}

// ---------------- split + transpose V: [b,t,h,d] fp32 -> [b,h,d,t] bf16 hi/lo ----------------
__global__ __launch_bounds__(256) void split_transpose_v(
    const float* __restrict__ V, __nv_bfloat16* __restrict__ vh,
    __nv_bfloat16* __restrict__ vl)
{
    __shared__ float tile[D_HEAD][33];   // [d][t]
    const int t0 = blockIdx.x * 32;
    const int hh = blockIdx.y, b = blockIdx.z;
    const int tid = threadIdx.x;
    for (int i = tid; i < 32 * D_HEAD; i += 256) {
        int t = i >> 7, d = i & 127;
        tile[d][t] = V[((size_t)(b * T_SEQ + t0 + t)) * D_MODEL + hh * D_HEAD + d];
    }
    __syncthreads();
    for (int i = tid; i < 32 * D_HEAD; i += 256) {
        int d = i >> 5, t = i & 31;
        float v = tile[d][t];
        __nv_bfloat16 h = __float2bfloat16(v);
        __nv_bfloat16 l = __float2bfloat16(v - __bfloat162float(h));
        size_t o = ((size_t)((b * N_HEADS + hh) * D_HEAD + d)) * T_SEQ + t0 + t;
        vh[o] = h; vl[o] = l;
    }
}

// ---------------- 3xBF16 mma.sync GEMM: C[M,N] = A[M,K] @ B[N,K]^T + bias ----------------
#define TM 128
#define TN 128
#define TKF 32
#define BSTR 40
#define REGION (TM * BSTR)
#define STAGE_E (4 * REGION)
#define GSTAGES 3
#define GEMM_SMEM (GSTAGES * STAGE_E * 2)

__global__ __launch_bounds__(256) void gemm_bf16(
    const __nv_bfloat16* __restrict__ Ah, const __nv_bfloat16* __restrict__ Al,
    const __nv_bfloat16* __restrict__ Wh, const __nv_bfloat16* __restrict__ Wl,
    const float* __restrict__ bias0, float* __restrict__ C0,
    const float* __restrict__ bias1, float* __restrict__ C1,
    const float* __restrict__ bias2, float* __restrict__ C2,
    int M, int N, int K)
{
    extern __shared__ __nv_bfloat16 smem[];
    const int tid = threadIdx.x;
    const int bz = blockIdx.z;
    const __nv_bfloat16* Bh = Wh + (size_t)bz * D_MODEL * D_MODEL;
    const __nv_bfloat16* Bl = Wl + (size_t)bz * D_MODEL * D_MODEL;
    const float* bia = (bz == 0) ? bias0 : (bz == 1) ? bias1 : bias2;
    float*       C   = (bz == 0) ? C0 : (bz == 1) ? C1 : C2;

    const int m0 = blockIdx.y * TM;
    const int n0 = blockIdx.x * TN;
    const int NTILES = K / TKF;

    const int lrow = tid >> 1;
    const int lhalf = tid & 1;
    const __nv_bfloat16* gAh = Ah + (size_t)(m0 + lrow) * K + lhalf * 16;
    const __nv_bfloat16* gAl = Al + (size_t)(m0 + lrow) * K + lhalf * 16;
    const __nv_bfloat16* gBh = Bh + (size_t)(n0 + lrow) * K + lhalf * 16;
    const __nv_bfloat16* gBl = Bl + (size_t)(n0 + lrow) * K + lhalf * 16;
    const uint32_t sbase = smem_u32(smem);
    const uint32_t sAh = sbase + (uint32_t)(lrow * BSTR + lhalf * 16) * 2u;
    const uint32_t sAl = sAh + REGION * 2u;
    const uint32_t sBh = sAh + 2u * REGION * 2u;
    const uint32_t sBl = sAh + 3u * REGION * 2u;

#define LOAD_TILE(t, s) do {                                                     \
        uint32_t _so = (uint32_t)((s) * STAGE_E) * 2u;                           \
        size_t _go = (size_t)(t) * TKF;                                          \
        _Pragma("unroll")                                                        \
        for (int _c = 0; _c < 2; _c++) {                                         \
            asm volatile("cp.async.cg.shared.global [%0], [%1], 16;"             \
                :: "r"(sAh + _so + _c * 16u), "l"(gAh + _go + _c * 8));          \
            asm volatile("cp.async.cg.shared.global [%0], [%1], 16;"             \
                :: "r"(sAl + _so + _c * 16u), "l"(gAl + _go + _c * 8));          \
            asm volatile("cp.async.cg.shared.global [%0], [%1], 16;"             \
                :: "r"(sBh + _so + _c * 16u), "l"(gBh + _go + _c * 8));          \
            asm volatile("cp.async.cg.shared.global [%0], [%1], 16;"             \
                :: "r"(sBl + _so + _c * 16u), "l"(gBl + _go + _c * 8));          \
        } } while (0)

    const int warp = tid >> 5, lane = tid & 31;
    const int wm = (warp >> 2) * 64, wn = (warp & 3) * 32;
    const int g = lane >> 2, tg = lane & 3;

    float c[4][4][4];
#pragma unroll
    for (int mi = 0; mi < 4; mi++)
#pragma unroll
        for (int ni = 0; ni < 4; ni++)
#pragma unroll
            for (int r = 0; r < 4; r++) c[mi][ni][r] = 0.f;

    LOAD_TILE(0, 0);
    asm volatile("cp.async.commit_group;" ::: "memory");
    LOAD_TILE(1, 1);
    asm volatile("cp.async.commit_group;" ::: "memory");

    const int aoff = (wm + g) * BSTR + 2 * tg;
    const int boff = (wn + g) * BSTR + 2 * tg;

    for (int kt = 0; kt < NTILES; kt++) {
        asm volatile("cp.async.wait_group 1;" ::: "memory");
        __syncthreads();

        int lt = kt + 2;
        if (lt < NTILES) LOAD_TILE(lt, lt % GSTAGES);
        asm volatile("cp.async.commit_group;" ::: "memory");

        const __nv_bfloat16* st = smem + (kt % GSTAGES) * STAGE_E;
        const __nv_bfloat16* pAh = st + aoff;
        const __nv_bfloat16* pAl = pAh + REGION;
        const __nv_bfloat16* pBh = st + 2 * REGION + boff;
        const __nv_bfloat16* pBl = pBh + REGION;

#pragma unroll
        for (int ks = 0; ks < 2; ks++) {
            const int kb = ks * 16;
            uint32_t ah[4][4], al[4][4], bh[4][2], bl[4][2];
#pragma unroll
            for (int mi = 0; mi < 4; mi++) {
                const int r1 = mi * 16 * BSTR + kb;
                const int r2 = r1 + 8 * BSTR;
                ah[mi][0] = *(const uint32_t*)(pAh + r1);
                ah[mi][1] = *(const uint32_t*)(pAh + r2);
                ah[mi][2] = *(const uint32_t*)(pAh + r1 + 8);
                ah[mi][3] = *(const uint32_t*)(pAh + r2 + 8);
                al[mi][0] = *(const uint32_t*)(pAl + r1);
                al[mi][1] = *(const uint32_t*)(pAl + r2);
                al[mi][2] = *(const uint32_t*)(pAl + r1 + 8);
                al[mi][3] = *(const uint32_t*)(pAl + r2 + 8);
            }
#pragma unroll
            for (int ni = 0; ni < 4; ni++) {
                const int rb = ni * 8 * BSTR + kb;
                bh[ni][0] = *(const uint32_t*)(pBh + rb);
                bh[ni][1] = *(const uint32_t*)(pBh + rb + 8);
                bl[ni][0] = *(const uint32_t*)(pBl + rb);
                bl[ni][1] = *(const uint32_t*)(pBl + rb + 8);
            }
#pragma unroll
            for (int mi = 0; mi < 4; mi++)
#pragma unroll
                for (int ni = 0; ni < 4; ni++) {
                    mma_bf16(c[mi][ni], ah[mi][0], ah[mi][1], ah[mi][2], ah[mi][3],
                             bl[ni][0], bl[ni][1]);
                    mma_bf16(c[mi][ni], al[mi][0], al[mi][1], al[mi][2], al[mi][3],
                             bh[ni][0], bh[ni][1]);
                    mma_bf16(c[mi][ni], ah[mi][0], ah[mi][1], ah[mi][2], ah[mi][3],
                             bh[ni][0], bh[ni][1]);
                }
        }
    }

#pragma unroll
    for (int ni = 0; ni < 4; ni++) {
        int col = n0 + wn + ni * 8 + 2 * tg;
        float2 bb = *(const float2*)(bia + col);
#pragma unroll
        for (int mi = 0; mi < 4; mi++) {
            int row = m0 + wm + mi * 16 + g;
            float2 o0, o1;
            o0.x = c[mi][ni][0] + bb.x; o0.y = c[mi][ni][1] + bb.y;
            o1.x = c[mi][ni][2] + bb.x; o1.y = c[mi][ni][3] + bb.y;
            *(float2*)(C + (size_t)row * N + col) = o0;
            *(float2*)(C + (size_t)(row + 8) * N + col) = o1;
        }
    }
#undef LOAD_TILE
}

// ---------------- fused RMSNorm + RoPE -> bf16 hi/lo (scaled) ----------------
__global__ __launch_bounds__(256) void rmsnorm_rope_bf(
    const float* __restrict__ hsrc, const float* __restrict__ w,
    const float* __restrict__ cosb, const float* __restrict__ sinb,
    __nv_bfloat16* __restrict__ oh, __nv_bfloat16* __restrict__ ol,
    float outscale)
{
    const int row = blockIdx.x;
    const int t = row & (T_SEQ - 1);
    const float* hp = hsrc + (size_t)row * D_MODEL;
    const float* cp = cosb + (size_t)t * D_MODEL;
    const float* sp = sinb + (size_t)t * D_MODEL;
    const int tid = threadIdx.x;

    float4 vals[2];
    float ss = 0.f;
#pragma unroll
    for (int i = 0; i < 2; i++) {
        float4 v = ((const float4*)hp)[tid + i * 256];
        vals[i] = v;
        ss += v.x * v.x + v.y * v.y + v.z * v.z + v.w * v.w;
    }
#pragma unroll
    for (int o = 16; o > 0; o >>= 1) ss += __shfl_xor_sync(0xffffffffu, ss, o);
    __shared__ float red[8];
    __shared__ float s_inv;
    if ((tid & 31) == 0) red[tid >> 5] = ss;
    __syncthreads();
    if (tid == 0) {
        float tot = 0.f;
#pragma unroll
        for (int i = 0; i < 8; i++) tot += red[i];
        s_inv = rsqrtf(tot * (1.0f / D_MODEL) + 1e-6f);
    }
    __syncthreads();
    const float inv = s_inv;

#pragma unroll
    for (int i = 0; i < 2; i++) {
        int fi = tid + i * 256;
        float4 v = vals[i];
        float4 wv = ((const float4*)w)[fi];
        float4 c4 = ((const float4*)cp)[fi];
        float4 s4 = ((const float4*)sp)[fi];
        float nx = v.x * inv * wv.x;
        float ny = v.y * inv * wv.y;
        float nz = v.z * inv * wv.z;
        float nw = v.w * inv * wv.w;
        float o0 = (nx * c4.x - ny * s4.x) * outscale;
        float o1 = (ny * c4.y + nx * s4.y) * outscale;
        float o2 = (nz * c4.z - nw * s4.z) * outscale;
        float o3 = (nw * c4.w + nz * s4.w) * outscale;
        __nv_bfloat16 h0 = __float2bfloat16(o0), h1 = __float2bfloat16(o1);
        __nv_bfloat16 h2 = __float2bfloat16(o2), h3 = __float2bfloat16(o3);
        __nv_bfloat16 l0 = __float2bfloat16(o0 - __bfloat162float(h0));
        __nv_bfloat16 l1 = __float2bfloat16(o1 - __bfloat162float(h1));
        __nv_bfloat16 l2 = __float2bfloat16(o2 - __bfloat162float(h2));
        __nv_bfloat16 l3 = __float2bfloat16(o3 - __bfloat162float(h3));
        __nv_bfloat162* hp2 = (__nv_bfloat162*)(oh + (size_t)row * D_MODEL + fi * 4);
        __nv_bfloat162* lp2 = (__nv_bfloat162*)(ol + (size_t)row * D_MODEL + fi * 4);
        hp2[0] = __nv_bfloat162(h0, h1); hp2[1] = __nv_bfloat162(h2, h3);
        lp2[0] = __nv_bfloat162(l0, l1); lp2[1] = __nv_bfloat162(l2, l3);
    }
}

// ---------------- tensor-core flash attention (3xBF16, non-causal) ----------------
#define AQ 128
#define AK 64
#define KSTR 136
#define VSTR 72
#define K_ELEMS (AK * KSTR)            // 8704
#define V_ELEMS (D_HEAD * VSTR)        // 9216
#define ASTAGE (2 * K_ELEMS + 2 * V_ELEMS)   // 35840 elems
#define ATTN_SMEM (2 * ASTAGE * 2)           // 143360 bytes

__global__ __launch_bounds__(256) void attn_tc(
    const __nv_bfloat16* __restrict__ Qh, const __nv_bfloat16* __restrict__ Ql,
    const __nv_bfloat16* __restrict__ Kh, const __nv_bfloat16* __restrict__ Kl,
    const __nv_bfloat16* __restrict__ Vth, const __nv_bfloat16* __restrict__ Vtl,
    float* __restrict__ Og)
{
    extern __shared__ __nv_bfloat16 asm_s[];
    const int tid = threadIdx.x, warp = tid >> 5, lane = tid & 31;
    const int g = lane >> 2, tg = lane & 3;
    const int h = blockIdx.y, b = blockIdx.z;
    const int q0 = blockIdx.x * AQ;
    const size_t tokbase = (size_t)b * T_SEQ;
    const uint32_t sbase = smem_u32(asm_s);
    const int NT = T_SEQ / AK;   // 32

    // ---- Q fragments in registers (16 rows per warp) ----
    const int qr = q0 + warp * 16;
    uint32_t qfh[8][4], qfl[8][4];
    {
        const __nv_bfloat16* bh_ = Qh + (tokbase + qr) * D_MODEL + h * D_HEAD;
        const __nv_bfloat16* bl_ = Ql + (tokbase + qr) * D_MODEL + h * D_HEAD;
#pragma unroll
        for (int ks = 0; ks < 8; ks++) {
            int k0 = ks * 16 + 2 * tg;
            qfh[ks][0] = *(const uint32_t*)(bh_ + (size_t)g * D_MODEL + k0);
            qfh[ks][1] = *(const uint32_t*)(bh_ + (size_t)(g + 8) * D_MODEL + k0);
            qfh[ks][2] = *(const uint32_t*)(bh_ + (size_t)g * D_MODEL + k0 + 8);
            qfh[ks][3] = *(const uint32_t*)(bh_ + (size_t)(g + 8) * D_MODEL + k0 + 8);
            qfl[ks][0] = *(const uint32_t*)(bl_ + (size_t)g * D_MODEL + k0);
            qfl[ks][1] = *(const uint32_t*)(bl_ + (size_t)(g + 8) * D_MODEL + k0);
            qfl[ks][2] = *(const uint32_t*)(bl_ + (size_t)g * D_MODEL + k0 + 8);
            qfl[ks][3] = *(const uint32_t*)(bl_ + (size_t)(g + 8) * D_MODEL + k0 + 8);
        }
    }

    float Oacc[16][4];
#pragma unroll
    for (int d = 0; d < 16; d++)
#pragma unroll
        for (int r = 0; r < 4; r++) Oacc[d][r] = 0.f;
    float mA = -1e30f, mB = -1e30f, lA = 0.f, lB = 0.f;

#define ALOAD(kt, s) do {                                                            \
        uint32_t _sb = sbase + (uint32_t)(s) * (ASTAGE * 2);                         \
        _Pragma("unroll")                                                            \
        for (int _i = 0; _i < 16; _i++) {                                            \
            int _c = tid + _i * 256;                                                 \
            const __nv_bfloat16* _src; uint32_t _dst;                                \
            if (_c < 2048) {                                                         \
                int _m = _c & 1023; int _row = _m >> 4, _j = _m & 15;                \
                const __nv_bfloat16* _bp = (_c < 1024) ? Kh : Kl;                    \
                _src = _bp + (tokbase + (size_t)(kt) * AK + _row) * D_MODEL          \
                       + h * D_HEAD + _j * 8;                                        \
                _dst = _sb + (uint32_t)(((_c < 1024) ? 0 : K_ELEMS)                  \
                       + _row * KSTR + _j * 8) * 2u;                                 \
            } else {                                                                 \
                int _m = (_c - 2048) & 1023; int _d = _m >> 3, _j = _m & 7;          \
                const __nv_bfloat16* _bp = (_c < 3072) ? Vth : Vtl;                  \
                _src = _bp + ((size_t)((b * N_HEADS + h) * D_HEAD + _d)) * T_SEQ     \
                       + (size_t)(kt) * AK + _j * 8;                                 \
                _dst = _sb + (uint32_t)(2 * K_ELEMS + ((_c < 3072) ? 0 : V_ELEMS)    \
                       + _d * VSTR + _j * 8) * 2u;                                   \
            }                                                                        \
            asm volatile("cp.async.cg.shared.global [%0], [%1], 16;"                 \
                         :: "r"(_dst), "l"(_src));                                   \
        } } while (0)

    ALOAD(0, 0);
    asm volatile("cp.async.commit_group;" ::: "memory");

    for (int kt = 0; kt < NT; kt++) {
        __syncthreads();   // all warps done with stage (kt-1)&1 before overwrite
        if (kt + 1 < NT) {
            ALOAD(kt + 1, (kt + 1) & 1);
            asm volatile("cp.async.commit_group;" ::: "memory");
            asm volatile("cp.async.wait_group 1;" ::: "memory");
        } else {
            asm volatile("cp.async.wait_group 0;" ::: "memory");
        }
        __syncthreads();

        const __nv_bfloat16* st = asm_s + (kt & 1) * ASTAGE;
        const __nv_bfloat16* pKh = st;
        const __nv_bfloat16* pKl = st + K_ELEMS;
        const __nv_bfloat16* pVh = st + 2 * K_ELEMS;
        const __nv_bfloat16* pVl = pVh + V_ELEMS;

        // ---- S = Q K^T (16 x 64 per warp) ----
        float sf[8][4];
#pragma unroll
        for (int n = 0; n < 8; n++) {
            float acc[4] = {0.f, 0.f, 0.f, 0.f};
#pragma unroll
            for (int ks = 0; ks < 8; ks++) {
                int off = (n * 8 + g) * KSTR + ks * 16 + 2 * tg;
                uint32_t kh0 = *(const uint32_t*)(pKh + off);
                uint32_t kh1 = *(const uint32_t*)(pKh + off + 8);
                uint32_t kl0 = *(const uint32_t*)(pKl + off);
                uint32_t kl1 = *(const uint32_t*)(pKl + off + 8);
                mma_bf16(acc, qfh[ks][0], qfh[ks][1], qfh[ks][2], qfh[ks][3], kl0, kl1);
                mma_bf16(acc, qfl[ks][0], qfl[ks][1], qfl[ks][2], qfl[ks][3], kh0, kh1);
                mma_bf16(acc, qfh[ks][0], qfh[ks][1], qfh[ks][2], qfh[ks][3], kh0, kh1);
            }
            sf[n][0] = acc[0]; sf[n][1] = acc[1]; sf[n][2] = acc[2]; sf[n][3] = acc[3];
        }

        // ---- online softmax (log2 domain; Q pre-scaled by scale*log2e) ----
        float tmA = fmaxf(sf[0][0], sf[0][1]);
        float tmB = fmaxf(sf[0][2], sf[0][3]);
#pragma unroll
        for (int n = 1; n < 8; n++) {
            tmA = fmaxf(tmA, fmaxf(sf[n][0], sf[n][1]));
            tmB = fmaxf(tmB, fmaxf(sf[n][2], sf[n][3]));
        }
        tmA = fmaxf(tmA, __shfl_xor_sync(0xffffffffu, tmA, 1));
        tmA = fmaxf(tmA, __shfl_xor_sync(0xffffffffu, tmA, 2));
        tmB = fmaxf(tmB, __shfl_xor_sync(0xffffffffu, tmB, 1));
        tmB = fmaxf(tmB, __shfl_xor_sync(0xffffffffu, tmB, 2));
        float mAn = fmaxf(mA, tmA), mBn = fmaxf(mB, tmB);
        float corrA = ex2f(mA - mAn), corrB = ex2f(mB - mBn);
        mA = mAn; mB = mBn;

        float sumA = 0.f, sumB = 0.f;
#pragma unroll
        for (int n = 0; n < 8; n++) {
            sf[n][0] = ex2f(sf[n][0] - mA);
            sf[n][1] = ex2f(sf[n][1] - mA);
            sf[n][2] = ex2f(sf[n][2] - mB);
            sf[n][3] = ex2f(sf[n][3] - mB);
            sumA += sf[n][0] + sf[n][1];
            sumB += sf[n][2] + sf[n][3];
        }
        sumA += __shfl_xor_sync(0xffffffffu, sumA, 1);
        sumA += __shfl_xor_sync(0xffffffffu, sumA, 2);
        sumB += __shfl_xor_sync(0xffffffffu, sumB, 1);
        sumB += __shfl_xor_sync(0xffffffffu, sumB, 2);
        lA = lA * corrA + sumA;
        lB = lB * corrB + sumB;

#pragma unroll
        for (int d = 0; d < 16; d++) {
            Oacc[d][0] *= corrA; Oacc[d][1] *= corrA;
            Oacc[d][2] *= corrB; Oacc[d][3] *= corrB;
        }

        // ---- P fragments (hi/lo bf16) ----
        uint32_t pfh[4][4], pfl[4][4];
#pragma unroll
        for (int kv = 0; kv < 4; kv++) {
#pragma unroll
            for (int half = 0; half < 2; half++) {
                int n = 2 * kv + half;
                float p0 = sf[n][0], p1 = sf[n][1], p2 = sf[n][2], p3 = sf[n][3];
                __nv_bfloat162 h01 = __floats2bfloat162_rn(p0, p1);
                __nv_bfloat162 h23 = __floats2bfloat162_rn(p2, p3);
                __nv_bfloat162 l01 = __floats2bfloat162_rn(
                    p0 - __bfloat162float(h01.x), p1 - __bfloat162float(h01.y));
                __nv_bfloat162 l23 = __floats2bfloat162_rn(
                    p2 - __bfloat162float(h23.x), p3 - __bfloat162float(h23.y));
                pfh[kv][0 + 2 * half] = *(uint32_t*)&h01;
                pfh[kv][1 + 2 * half] = *(uint32_t*)&h23;
                pfl[kv][0 + 2 * half] = *(uint32_t*)&l01;
                pfl[kv][1 + 2 * half] = *(uint32_t*)&l23;
            }
        }

        // ---- O += P V ----
#pragma unroll
        for (int d = 0; d < 16; d++) {
#pragma unroll
            for (int kv = 0; kv < 4; kv++) {
                int off = (d * 8 + g) * VSTR + kv * 16 + 2 * tg;
                uint32_t vh0 = *(const uint32_t*)(pVh + off);
                uint32_t vh1 = *(const uint32_t*)(pVh + off + 8);
                uint32_t vl0 = *(const uint32_t*)(pVl + off);
                uint32_t vl1 = *(const uint32_t*)(pVl + off + 8);
                mma_bf16(Oacc[d], pfh[kv][0], pfh[kv][1], pfh[kv][2], pfh[kv][3], vl0, vl1);
                mma_bf16(Oacc[d], pfl[kv][0], pfl[kv][1], pfl[kv][2], pfl[kv][3], vh0, vh1);
                mma_bf16(Oacc[d], pfh[kv][0], pfh[kv][1], pfh[kv][2], pfh[kv][3], vh0, vh1);
            }
        }
    }

    // ---- finalize ----
    float liA = 1.0f / lA, liB = 1.0f / lB;
    float* OrA = Og + (tokbase + qr + g) * D_MODEL + h * D_HEAD;
    float* OrB = Og + (tokbase + qr + g + 8) * D_MODEL + h * D_HEAD;
#pragma unroll
    for (int d = 0; d < 16; d++) {
        float2 oA, oB;
        oA.x = Oacc[d][0] * liA; oA.y = Oacc[d][1] * liA;
        oB.x = Oacc[d][2] * liB; oB.y = Oacc[d][3] * liB;
        *(float2*)(OrA + d * 8 + 2 * tg) = oA;
        *(float2*)(OrB + d * 8 + 2 * tg) = oB;
    }
#undef ALOAD
}

// ---------------- host launch ----------------
extern "C" void kernel_launch(void* const* d_in, const int* in_sizes, int n_in,
                              void* d_out, int out_size)
{
    const float* x   = (const float*)d_in[0];
    const float* cosb= (const float*)d_in[1];
    const float* sinb= (const float*)d_in[2];
    const float* Wq  = (const float*)d_in[3];
    const float* bq  = (const float*)d_in[4];
    const float* Wk  = (const float*)d_in[5];
    const float* bk  = (const float*)d_in[6];
    const float* Wv  = (const float*)d_in[7];
    const float* bv  = (const float*)d_in[8];
    const float* qnw = (const float*)d_in[9];
    const float* knw = (const float*)d_in[10];
    const float* Wo  = (const float*)d_in[11];
    const float* bo  = (const float*)d_in[12];
    float* out = (float*)d_out;

    const int BT = in_sizes[0] / D_MODEL;    // 4096
    const int Bb = BT / T_SEQ;               // 2

    float *qp, *kp, *vp, *ap;
    cudaGetSymbolAddress((void**)&qp, g_q);
    cudaGetSymbolAddress((void**)&kp, g_k);
    cudaGetSymbolAddress((void**)&vp, g_v);
    cudaGetSymbolAddress((void**)&ap, g_attn);
    __nv_bfloat16 *xh, *xl, *wh, *wl, *ah, *al, *qh, *ql, *kh, *kl, *vth, *vtl;
    cudaGetSymbolAddress((void**)&xh, g_xh);
    cudaGetSymbolAddress((void**)&xl, g_xl);
    cudaGetSymbolAddress((void**)&wh, g_wh);
    cudaGetSymbolAddress((void**)&wl, g_wl);
    cudaGetSymbolAddress((void**)&ah, g_ah);
    cudaGetSymbolAddress((void**)&al, g_al);
    cudaGetSymbolAddress((void**)&qh, g_qh);
    cudaGetSymbolAddress((void**)&ql, g_ql);
    cudaGetSymbolAddress((void**)&kh, g_kh);
    cudaGetSymbolAddress((void**)&kl, g_kl);
    cudaGetSymbolAddress((void**)&vth, g_vth);
    cudaGetSymbolAddress((void**)&vtl, g_vtl);

    cudaFuncSetAttribute(gemm_bf16, cudaFuncAttributeMaxDynamicSharedMemorySize, GEMM_SMEM);
    cudaFuncSetAttribute(attn_tc, cudaFuncAttributeMaxDynamicSharedMemorySize, ATTN_SMEM);

    const int nX4 = BT * D_MODEL / 4;
    const int nW4 = D_MODEL * D_MODEL / 4;
    const size_t woff = (size_t)D_MODEL * D_MODEL;

    split_bf16<<<(nX4 + 255) / 256, 256>>>(x, xh, xl, nX4);
    split_bf16<<<(nW4 + 255) / 256, 256>>>(Wq, wh + 0 * woff, wl + 0 * woff, nW4);
    split_bf16<<<(nW4 + 255) / 256, 256>>>(Wk, wh + 1 * woff, wl + 1 * woff, nW4);
    split_bf16<<<(nW4 + 255) / 256, 256>>>(Wv, wh + 2 * woff, wl + 2 * woff, nW4);
    split_bf16<<<(nW4 + 255) / 256, 256>>>(Wo, wh + 3 * woff, wl + 3 * woff, nW4);

    dim3 gq(D_MODEL / TN, BT / TM, 3);
    gemm_bf16<<<gq, 256, GEMM_SMEM>>>(xh, xl, wh, wl,
                                      bq, qp, bk, kp, bv, vp,
                                      BT, D_MODEL, D_MODEL);

    // scale = 1/sqrt(Dh) * log2(e)  (softmax runs in exp2 domain)
    const float qscale = 0.08838834764831845f * 1.4426950408889634f;
    rmsnorm_rope_bf<<<BT, 256>>>(qp, qnw, cosb, sinb, qh, ql, qscale);
    rmsnorm_rope_bf<<<BT, 256>>>(kp, knw, cosb, sinb, kh, kl, 1.0f);

    dim3 vt(T_SEQ / 32, N_HEADS, Bb);
    split_transpose_v<<<vt, 256>>>(vp, vth, vtl);

    dim3 adim(T_SEQ / AQ, N_HEADS, Bb);   // (16, 16, 2)
    attn_tc<<<adim, 256, ATTN_SMEM>>>(qh, ql, kh, kl, vth, vtl, ap);

    split_bf16<<<(nX4 + 255) / 256, 256>>>(ap, ah, al, nX4);
    dim3 go(D_MODEL / TN, BT / TM, 1);
    gemm_bf16<<<go, 256, GEMM_SMEM>>>(ah, al, wh + 3 * woff, wl + 3 * woff,
                                      bo, out, bo, out, bo, out,
                                      BT, D_MODEL, D_MODEL);
}

// round 7
// speedup vs baseline: 2.9844x; 1.0436x over previous
#include <cuda_runtime.h>
#include <cuda_bf16.h>
#include <cstdint>
#include <math.h>

#define D_MODEL 2048
#define T_SEQ   2048
#define N_HEADS 16
#define D_HEAD  128
#define BT_MAX  4096   // B=2 * T=2048

// ---------------- scratch (device globals; allocation-free) ----------------
__device__ float g_q[(size_t)BT_MAX * D_MODEL];
__device__ float g_k[(size_t)BT_MAX * D_MODEL];
__device__ float g_v[(size_t)BT_MAX * D_MODEL];

__device__ __nv_bfloat16 g_xh[(size_t)BT_MAX * D_MODEL];
__device__ __nv_bfloat16 g_xl[(size_t)BT_MAX * D_MODEL];
__device__ __nv_bfloat16 g_wh[(size_t)4 * D_MODEL * D_MODEL];  // Wq,Wk,Wv,Wo hi
__device__ __nv_bfloat16 g_wl[(size_t)4 * D_MODEL * D_MODEL];  // lo
__device__ __nv_bfloat16 g_ah[(size_t)BT_MAX * D_MODEL];       // attn out hi
__device__ __nv_bfloat16 g_al[(size_t)BT_MAX * D_MODEL];

__device__ __nv_bfloat16 g_qh[(size_t)BT_MAX * D_MODEL];       // Q hi (scaled)
__device__ __nv_bfloat16 g_ql[(size_t)BT_MAX * D_MODEL];
__device__ __nv_bfloat16 g_kh[(size_t)BT_MAX * D_MODEL];       // K hi
__device__ __nv_bfloat16 g_kl[(size_t)BT_MAX * D_MODEL];
__device__ __nv_bfloat16 g_vth[(size_t)BT_MAX * D_MODEL];      // V^T hi [b,h,d,t]
__device__ __nv_bfloat16 g_vtl[(size_t)BT_MAX * D_MODEL];

__device__ __forceinline__ uint32_t smem_u32(const void* p) {
    uint32_t a;
    asm("{ .reg .u64 t; cvta.to.shared.u64 t, %1; cvt.u32.u64 %0, t; }" : "=r"(a) : "l"(p));
    return a;
}

__device__ __forceinline__ void mma_bf16(float* c, uint32_t a0, uint32_t a1,
                                         uint32_t a2, uint32_t a3,
                                         uint32_t b0, uint32_t b1) {
    asm volatile(
        "mma.sync.aligned.m16n8k16.row.col.f32.bf16.bf16.f32 "
        "{%0,%1,%2,%3}, {%4,%5,%6,%7}, {%8,%9}, {%0,%1,%2,%3};"
        : "+f"(c[0]), "+f"(c[1]), "+f"(c[2]), "+f"(c[3])
        : "r"(a0), "r"(a1), "r"(a2), "r"(a3), "r"(b0), "r"(b1));
}

#define LDSM4(r, a) asm volatile(                                                  \
    "ldmatrix.sync.aligned.m8n8.x4.shared.b16 {%0,%1,%2,%3}, [%4];"                \
    : "=r"((r)[0]), "=r"((r)[1]), "=r"((r)[2]), "=r"((r)[3]) : "r"(a))

__device__ __forceinline__ float ex2f(float x) {
    float r;
    asm("ex2.approx.f32 %0, %1;" : "=f"(r) : "f"(x));
    return r;
}

// ---------------- split fp32 -> bf16 hi + bf16 lo ----------------
__global__ __launch_bounds__(256) void split_bf16(
    const float* __restrict__ src, __nv_bfloat16* __restrict__ hi,
    __nv_bfloat16* __restrict__ lo, int n4)
{
    int i = blockIdx.x * 256 + threadIdx.x;
    if (i >= n4) return;
    float4 v = ((const float4*)src)[i];
    __nv_bfloat16 h0 = __float2bfloat16(v.x);
    __nv_bfloat16 h1 = __float2bfloat16(v.y);
    __nv_bfloat16 h2 = __float2bfloat16(v.z);
    __nv_bfloat16 h3 = __float2bfloat16(v.w);
    __nv_bfloat16 l0 = __float2bfloat16(v.x - __bfloat162float(h0));
    __nv_bfloat16 l1 = __float2bfloat16(v.y - __bfloat162float(h1));
    __nv_bfloat16 l2 = __float2bfloat16(v.z - __bfloat162float(h2));
    __nv_bfloat16 l3 = __float2bfloat16(v.w - __bfloat162float(h3));
    __nv_bfloat162* hp = (__nv_bfloat162*)(hi + (size_t)i * 4);
    __nv_bfloat162* lp = (__nv_bfloat162*)(lo + (size_t)i * 4);
    hp[0] = __nv_bfloat162(h0, h1); hp[1] = __nv_bfloat162(h2, h3);
    lp[0] = __nv_bfloat162(l0, l1); lp[1] = __nv_bfloat162(l2, l3);
}

// ---------------- split + transpose V: [b,t,h,d] fp32 -> [b,h,d,t] bf16 hi/lo ----------------
__global__ __launch_bounds__(256) void split_transpose_v(
    const float* __restrict__ V, __nv_bfloat16* __restrict__ vh,
    __nv_bfloat16* __restrict__ vl)
{
    __shared__ float tile[D_HEAD][33];
    const int t0 = blockIdx.x * 32;
    const int hh = blockIdx.y, b = blockIdx.z;
    const int tid = threadIdx.x;
    for (int i = tid; i < 32 * D_HEAD; i += 256) {
        int t = i >> 7, d = i & 127;
        tile[d][t] = V[((size_t)(b * T_SEQ + t0 + t)) * D_MODEL + hh * D_HEAD + d];
    }
    __syncthreads();
    for (int i = tid; i < 32 * D_HEAD; i += 256) {
        int d = i >> 5, t = i & 31;
        float v = tile[d][t];
        __nv_bfloat16 h = __float2bfloat16(v);
        __nv_bfloat16 l = __float2bfloat16(v - __bfloat162float(h));
        size_t o = ((size_t)((b * N_HEADS + hh) * D_HEAD + d)) * T_SEQ + t0 + t;
        vh[o] = h; vl[o] = l;
    }
}

// ---------------- 3xBF16 mma.sync GEMM (ldmatrix): C = A @ B^T + bias ----------------
#define TM 128
#define TN 128
#define TKF 32
#define BSTR 40
#define REGION (TM * BSTR)
#define STAGE_E (4 * REGION)
#define GSTAGES 3
#define GEMM_SMEM (GSTAGES * STAGE_E * 2)

__global__ __launch_bounds__(256) void gemm_bf16(
    const __nv_bfloat16* __restrict__ Ah, const __nv_bfloat16* __restrict__ Al,
    const __nv_bfloat16* __restrict__ Wh, const __nv_bfloat16* __restrict__ Wl,
    const float* __restrict__ bias0, float* __restrict__ C0,
    const float* __restrict__ bias1, float* __restrict__ C1,
    const float* __restrict__ bias2, float* __restrict__ C2,
    int M, int N, int K)
{
    extern __shared__ __nv_bfloat16 smem[];
    const int tid = threadIdx.x;
    const int bz = blockIdx.z;
    const __nv_bfloat16* Bh = Wh + (size_t)bz * D_MODEL * D_MODEL;
    const __nv_bfloat16* Bl = Wl + (size_t)bz * D_MODEL * D_MODEL;
    const float* bia = (bz == 0) ? bias0 : (bz == 1) ? bias1 : bias2;
    float*       C   = (bz == 0) ? C0 : (bz == 1) ? C1 : C2;

    const int m0 = blockIdx.y * TM;
    const int n0 = blockIdx.x * TN;
    const int NTILES = K / TKF;

    const int lrow = tid >> 1;
    const int lhalf = tid & 1;
    const __nv_bfloat16* gAh = Ah + (size_t)(m0 + lrow) * K + lhalf * 16;
    const __nv_bfloat16* gAl = Al + (size_t)(m0 + lrow) * K + lhalf * 16;
    const __nv_bfloat16* gBh = Bh + (size_t)(n0 + lrow) * K + lhalf * 16;
    const __nv_bfloat16* gBl = Bl + (size_t)(n0 + lrow) * K + lhalf * 16;
    const uint32_t sbase = smem_u32(smem);
    const uint32_t sAh = sbase + (uint32_t)(lrow * BSTR + lhalf * 16) * 2u;
    const uint32_t sAl = sAh + REGION * 2u;
    const uint32_t sBh = sAh + 2u * REGION * 2u;
    const uint32_t sBl = sAh + 3u * REGION * 2u;

#define LOAD_TILE(t, s) do {                                                     \
        uint32_t _so = (uint32_t)((s) * STAGE_E) * 2u;                           \
        size_t _go = (size_t)(t) * TKF;                                          \
        _Pragma("unroll")                                                        \
        for (int _c = 0; _c < 2; _c++) {                                         \
            asm volatile("cp.async.cg.shared.global [%0], [%1], 16;"             \
                :: "r"(sAh + _so + _c * 16u), "l"(gAh + _go + _c * 8));          \
            asm volatile("cp.async.cg.shared.global [%0], [%1], 16;"             \
                :: "r"(sAl + _so + _c * 16u), "l"(gAl + _go + _c * 8));          \
            asm volatile("cp.async.cg.shared.global [%0], [%1], 16;"             \
                :: "r"(sBh + _so + _c * 16u), "l"(gBh + _go + _c * 8));          \
            asm volatile("cp.async.cg.shared.global [%0], [%1], 16;"             \
                :: "r"(sBl + _so + _c * 16u), "l"(gBl + _go + _c * 8));          \
        } } while (0)

    const int warp = tid >> 5, lane = tid & 31;
    const int wm = (warp >> 2) * 64, wn = (warp & 3) * 32;
    const int g = lane >> 2, tg = lane & 3;

    // ldmatrix lane address bases (bytes, relative to stage start)
    const uint32_t aLane = (uint32_t)(((wm + (lane & 15)) * BSTR) + ((lane >> 4) * 8)) * 2u;
    const int bnrow = wn + (lane & 7) + ((lane & 16) ? 8 : 0);
    const uint32_t bLane = (uint32_t)(bnrow * BSTR + ((lane & 8) ? 8 : 0)) * 2u
                         + 2u * REGION * 2u;

    float c[4][4][4];
#pragma unroll
    for (int mi = 0; mi < 4; mi++)
#pragma unroll
        for (int ni = 0; ni < 4; ni++)
#pragma unroll
            for (int r = 0; r < 4; r++) c[mi][ni][r] = 0.f;

    LOAD_TILE(0, 0);
    asm volatile("cp.async.commit_group;" ::: "memory");
    LOAD_TILE(1, 1);
    asm volatile("cp.async.commit_group;" ::: "memory");

    for (int kt = 0; kt < NTILES; kt++) {
        asm volatile("cp.async.wait_group 1;" ::: "memory");
        __syncthreads();

        int lt = kt + 2;
        if (lt < NTILES) LOAD_TILE(lt, lt % GSTAGES);
        asm volatile("cp.async.commit_group;" ::: "memory");

        const uint32_t stb = sbase + (uint32_t)((kt % GSTAGES) * STAGE_E) * 2u;
        const uint32_t aB = stb + aLane;
        const uint32_t bB = stb + bLane;

#pragma unroll
        for (int ks = 0; ks < 2; ks++) {
            uint32_t ah[4][4], al[4][4], bh[2][4], bl[2][4];
#pragma unroll
            for (int mi = 0; mi < 4; mi++) {
                uint32_t ad = aB + (uint32_t)(mi * 16 * BSTR + ks * 16) * 2u;
                LDSM4(ah[mi], ad);
                LDSM4(al[mi], ad + REGION * 2u);
            }
#pragma unroll
            for (int p = 0; p < 2; p++) {
                uint32_t bd = bB + (uint32_t)(p * 16 * BSTR + ks * 16) * 2u;
                LDSM4(bh[p], bd);
                LDSM4(bl[p], bd + REGION * 2u);
            }
#pragma unroll
            for (int mi = 0; mi < 4; mi++)
#pragma unroll
                for (int ni = 0; ni < 4; ni++) {
                    const int p = ni >> 1, hf = (ni & 1) * 2;
                    mma_bf16(c[mi][ni], ah[mi][0], ah[mi][1], ah[mi][2], ah[mi][3],
                             bl[p][hf], bl[p][hf + 1]);
                    mma_bf16(c[mi][ni], al[mi][0], al[mi][1], al[mi][2], al[mi][3],
                             bh[p][hf], bh[p][hf + 1]);
                    mma_bf16(c[mi][ni], ah[mi][0], ah[mi][1], ah[mi][2], ah[mi][3],
                             bh[p][hf], bh[p][hf + 1]);
                }
        }
    }

#pragma unroll
    for (int ni = 0; ni < 4; ni++) {
        int col = n0 + wn + ni * 8 + 2 * tg;
        float2 bb = *(const float2*)(bia + col);
#pragma unroll
        for (int mi = 0; mi < 4; mi++) {
            int row = m0 + wm + mi * 16 + g;
            float2 o0, o1;
            o0.x = c[mi][ni][0] + bb.x; o0.y = c[mi][ni][1] + bb.y;
            o1.x = c[mi][ni][2] + bb.x; o1.y = c[mi][ni][3] + bb.y;
            *(float2*)(C + (size_t)row * N + col) = o0;
            *(float2*)(C + (size_t)(row + 8) * N + col) = o1;
        }
    }
#undef LOAD_TILE
}

// ---------------- fused RMSNorm + RoPE -> bf16 hi/lo (scaled) ----------------
__global__ __launch_bounds__(256) void rmsnorm_rope_bf(
    const float* __restrict__ hsrc, const float* __restrict__ w,
    const float* __restrict__ cosb, const float* __restrict__ sinb,
    __nv_bfloat16* __restrict__ oh, __nv_bfloat16* __restrict__ ol,
    float outscale)
{
    const int row = blockIdx.x;
    const int t = row & (T_SEQ - 1);
    const float* hp = hsrc + (size_t)row * D_MODEL;
    const float* cp = cosb + (size_t)t * D_MODEL;
    const float* sp = sinb + (size_t)t * D_MODEL;
    const int tid = threadIdx.x;

    float4 vals[2];
    float ss = 0.f;
#pragma unroll
    for (int i = 0; i < 2; i++) {
        float4 v = ((const float4*)hp)[tid + i * 256];
        vals[i] = v;
        ss += v.x * v.x + v.y * v.y + v.z * v.z + v.w * v.w;
    }
#pragma unroll
    for (int o = 16; o > 0; o >>= 1) ss += __shfl_xor_sync(0xffffffffu, ss, o);
    __shared__ float red[8];
    __shared__ float s_inv;
    if ((tid & 31) == 0) red[tid >> 5] = ss;
    __syncthreads();
    if (tid == 0) {
        float tot = 0.f;
#pragma unroll
        for (int i = 0; i < 8; i++) tot += red[i];
        s_inv = rsqrtf(tot * (1.0f / D_MODEL) + 1e-6f);
    }
    __syncthreads();
    const float inv = s_inv;

#pragma unroll
    for (int i = 0; i < 2; i++) {
        int fi = tid + i * 256;
        float4 v = vals[i];
        float4 wv = ((const float4*)w)[fi];
        float4 c4 = ((const float4*)cp)[fi];
        float4 s4 = ((const float4*)sp)[fi];
        float nx = v.x * inv * wv.x;
        float ny = v.y * inv * wv.y;
        float nz = v.z * inv * wv.z;
        float nw = v.w * inv * wv.w;
        float o0 = (nx * c4.x - ny * s4.x) * outscale;
        float o1 = (ny * c4.y + nx * s4.y) * outscale;
        float o2 = (nz * c4.z - nw * s4.z) * outscale;
        float o3 = (nw * c4.w + nz * s4.w) * outscale;
        __nv_bfloat16 h0 = __float2bfloat16(o0), h1 = __float2bfloat16(o1);
        __nv_bfloat16 h2 = __float2bfloat16(o2), h3 = __float2bfloat16(o3);
        __nv_bfloat16 l0 = __float2bfloat16(o0 - __bfloat162float(h0));
        __nv_bfloat16 l1 = __float2bfloat16(o1 - __bfloat162float(h1));
        __nv_bfloat16 l2 = __float2bfloat16(o2 - __bfloat162float(h2));
        __nv_bfloat16 l3 = __float2bfloat16(o3 - __bfloat162float(h3));
        __nv_bfloat162* hp2 = (__nv_bfloat162*)(oh + (size_t)row * D_MODEL + fi * 4);
        __nv_bfloat162* lp2 = (__nv_bfloat162*)(ol + (size_t)row * D_MODEL + fi * 4);
        hp2[0] = __nv_bfloat162(h0, h1); hp2[1] = __nv_bfloat162(h2, h3);
        lp2[0] = __nv_bfloat162(l0, l1); lp2[1] = __nv_bfloat162(l2, l3);
    }
}

// ---------------- tensor-core flash attention (3xBF16, ldmatrix) ----------------
#define AQ 128
#define AK 64
#define KSTR 136
#define VSTR 72
#define K_ELEMS (AK * KSTR)
#define V_ELEMS (D_HEAD * VSTR)
#define ASTAGE (2 * K_ELEMS + 2 * V_ELEMS)
#define ATTN_SMEM (2 * ASTAGE * 2)

__global__ __launch_bounds__(256) void attn_tc(
    const __nv_bfloat16* __restrict__ Qh, const __nv_bfloat16* __restrict__ Ql,
    const __nv_bfloat16* __restrict__ Kh, const __nv_bfloat16* __restrict__ Kl,
    const __nv_bfloat16* __restrict__ Vth, const __nv_bfloat16* __restrict__ Vtl,
    __nv_bfloat16* __restrict__ Oh, __nv_bfloat16* __restrict__ Ol)
{
    extern __shared__ __nv_bfloat16 asm_s[];
    const int tid = threadIdx.x, warp = tid >> 5, lane = tid & 31;
    const int g = lane >> 2, tg = lane & 3;
    const int h = blockIdx.y, b = blockIdx.z;
    const int q0 = blockIdx.x * AQ;
    const size_t tokbase = (size_t)b * T_SEQ;
    const uint32_t sbase = smem_u32(asm_s);
    const int NT = T_SEQ / AK;

    // ldmatrix lane bases (bytes within a stage)
    const int lrow16 = (lane & 7) + ((lane & 16) ? 8 : 0);
    const int lkh = (lane & 8) ? 8 : 0;
    const uint32_t kLane = (uint32_t)(lrow16 * KSTR + lkh) * 2u;
    const uint32_t vLane = (uint32_t)(lrow16 * VSTR + lkh) * 2u + (uint32_t)(2 * K_ELEMS) * 2u;

    // ---- Q fragments in registers (16 rows per warp) ----
    const int qr = q0 + warp * 16;
    uint32_t qfh[8][4], qfl[8][4];
    {
        const __nv_bfloat16* bh_ = Qh + (tokbase + qr) * D_MODEL + h * D_HEAD;
        const __nv_bfloat16* bl_ = Ql + (tokbase + qr) * D_MODEL + h * D_HEAD;
#pragma unroll
        for (int ks = 0; ks < 8; ks++) {
            int k0 = ks * 16 + 2 * tg;
            qfh[ks][0] = *(const uint32_t*)(bh_ + (size_t)g * D_MODEL + k0);
            qfh[ks][1] = *(const uint32_t*)(bh_ + (size_t)(g + 8) * D_MODEL + k0);
            qfh[ks][2] = *(const uint32_t*)(bh_ + (size_t)g * D_MODEL + k0 + 8);
            qfh[ks][3] = *(const uint32_t*)(bh_ + (size_t)(g + 8) * D_MODEL + k0 + 8);
            qfl[ks][0] = *(const uint32_t*)(bl_ + (size_t)g * D_MODEL + k0);
            qfl[ks][1] = *(const uint32_t*)(bl_ + (size_t)(g + 8) * D_MODEL + k0);
            qfl[ks][2] = *(const uint32_t*)(bl_ + (size_t)g * D_MODEL + k0 + 8);
            qfl[ks][3] = *(const uint32_t*)(bl_ + (size_t)(g + 8) * D_MODEL + k0 + 8);
        }
    }

    float Oacc[16][4];
#pragma unroll
    for (int d = 0; d < 16; d++)
#pragma unroll
        for (int r = 0; r < 4; r++) Oacc[d][r] = 0.f;
    float mA = -1e30f, mB = -1e30f, lA = 0.f, lB = 0.f;

#define ALOAD(kt, s) do {                                                            \
        uint32_t _sb = sbase + (uint32_t)(s) * (ASTAGE * 2);                         \
        _Pragma("unroll")                                                            \
        for (int _i = 0; _i < 16; _i++) {                                            \
            int _c = tid + _i * 256;                                                 \
            const __nv_bfloat16* _src; uint32_t _dst;                                \
            if (_c < 2048) {                                                         \
                int _m = _c & 1023; int _row = _m >> 4, _j = _m & 15;                \
                const __nv_bfloat16* _bp = (_c < 1024) ? Kh : Kl;                    \
                _src = _bp + (tokbase + (size_t)(kt) * AK + _row) * D_MODEL          \
                       + h * D_HEAD + _j * 8;                                        \
                _dst = _sb + (uint32_t)(((_c < 1024) ? 0 : K_ELEMS)                  \
                       + _row * KSTR + _j * 8) * 2u;                                 \
            } else {                                                                 \
                int _m = (_c - 2048) & 1023; int _d = _m >> 3, _j = _m & 7;          \
                const __nv_bfloat16* _bp = (_c < 3072) ? Vth : Vtl;                  \
                _src = _bp + ((size_t)((b * N_HEADS + h) * D_HEAD + _d)) * T_SEQ     \
                       + (size_t)(kt) * AK + _j * 8;                                 \
                _dst = _sb + (uint32_t)(2 * K_ELEMS + ((_c < 3072) ? 0 : V_ELEMS)    \
                       + _d * VSTR + _j * 8) * 2u;                                   \
            }                                                                        \
            asm volatile("cp.async.cg.shared.global [%0], [%1], 16;"                 \
                         :: "r"(_dst), "l"(_src));                                   \
        } } while (0)

    ALOAD(0, 0);
    asm volatile("cp.async.commit_group;" ::: "memory");

    for (int kt = 0; kt < NT; kt++) {
        __syncthreads();
        if (kt + 1 < NT) {
            ALOAD(kt + 1, (kt + 1) & 1);
            asm volatile("cp.async.commit_group;" ::: "memory");
            asm volatile("cp.async.wait_group 1;" ::: "memory");
        } else {
            asm volatile("cp.async.wait_group 0;" ::: "memory");
        }
        __syncthreads();

        const uint32_t stb = sbase + (uint32_t)((kt & 1) * ASTAGE) * 2u;
        const uint32_t kB = stb + kLane;
        const uint32_t vB = stb + vLane;

        // ---- S = Q K^T (16 x 64 per warp) ----
        float sf[8][4];
#pragma unroll
        for (int p = 0; p < 4; p++) {
            float acc0[4] = {0.f, 0.f, 0.f, 0.f};
            float acc1[4] = {0.f, 0.f, 0.f, 0.f};
#pragma unroll
            for (int ks = 0; ks < 8; ks++) {
                uint32_t ad = kB + (uint32_t)(p * 16 * KSTR + ks * 16) * 2u;
                uint32_t kh[4], kl[4];
                LDSM4(kh, ad);
                LDSM4(kl, ad + (uint32_t)K_ELEMS * 2u);
                mma_bf16(acc0, qfh[ks][0], qfh[ks][1], qfh[ks][2], qfh[ks][3], kl[0], kl[1]);
                mma_bf16(acc0, qfl[ks][0], qfl[ks][1], qfl[ks][2], qfl[ks][3], kh[0], kh[1]);
                mma_bf16(acc0, qfh[ks][0], qfh[ks][1], qfh[ks][2], qfh[ks][3], kh[0], kh[1]);
                mma_bf16(acc1, qfh[ks][0], qfh[ks][1], qfh[ks][2], qfh[ks][3], kl[2], kl[3]);
                mma_bf16(acc1, qfl[ks][0], qfl[ks][1], qfl[ks][2], qfl[ks][3], kh[2], kh[3]);
                mma_bf16(acc1, qfh[ks][0], qfh[ks][1], qfh[ks][2], qfh[ks][3], kh[2], kh[3]);
            }
#pragma unroll
            for (int r = 0; r < 4; r++) {
                sf[2 * p][r] = acc0[r];
                sf[2 * p + 1][r] = acc1[r];
            }
        }

        // ---- online softmax (exp2 domain; Q pre-scaled by scale*log2e) ----
        float tmA = fmaxf(sf[0][0], sf[0][1]);
        float tmB = fmaxf(sf[0][2], sf[0][3]);
#pragma unroll
        for (int n = 1; n < 8; n++) {
            tmA = fmaxf(tmA, fmaxf(sf[n][0], sf[n][1]));
            tmB = fmaxf(tmB, fmaxf(sf[n][2], sf[n][3]));
        }
        tmA = fmaxf(tmA, __shfl_xor_sync(0xffffffffu, tmA, 1));
        tmA = fmaxf(tmA, __shfl_xor_sync(0xffffffffu, tmA, 2));
        tmB = fmaxf(tmB, __shfl_xor_sync(0xffffffffu, tmB, 1));
        tmB = fmaxf(tmB, __shfl_xor_sync(0xffffffffu, tmB, 2));
        float mAn = fmaxf(mA, tmA), mBn = fmaxf(mB, tmB);
        float corrA = ex2f(mA - mAn), corrB = ex2f(mB - mBn);
        mA = mAn; mB = mBn;

        float sumA = 0.f, sumB = 0.f;
#pragma unroll
        for (int n = 0; n < 8; n++) {
            sf[n][0] = ex2f(sf[n][0] - mA);
            sf[n][1] = ex2f(sf[n][1] - mA);
            sf[n][2] = ex2f(sf[n][2] - mB);
            sf[n][3] = ex2f(sf[n][3] - mB);
            sumA += sf[n][0] + sf[n][1];
            sumB += sf[n][2] + sf[n][3];
        }
        sumA += __shfl_xor_sync(0xffffffffu, sumA, 1);
        sumA += __shfl_xor_sync(0xffffffffu, sumA, 2);
        sumB += __shfl_xor_sync(0xffffffffu, sumB, 1);
        sumB += __shfl_xor_sync(0xffffffffu, sumB, 2);
        lA = lA * corrA + sumA;
        lB = lB * corrB + sumB;

#pragma unroll
        for (int d = 0; d < 16; d++) {
            Oacc[d][0] *= corrA; Oacc[d][1] *= corrA;
            Oacc[d][2] *= corrB; Oacc[d][3] *= corrB;
        }

        // ---- P fragments (hi/lo bf16) ----
        uint32_t pfh[4][4], pfl[4][4];
#pragma unroll
        for (int kv = 0; kv < 4; kv++) {
#pragma unroll
            for (int half = 0; half < 2; half++) {
                int n = 2 * kv + half;
                float p0 = sf[n][0], p1 = sf[n][1], p2 = sf[n][2], p3 = sf[n][3];
                __nv_bfloat162 h01 = __floats2bfloat162_rn(p0, p1);
                __nv_bfloat162 h23 = __floats2bfloat162_rn(p2, p3);
                __nv_bfloat162 l01 = __floats2bfloat162_rn(
                    p0 - __bfloat162float(h01.x), p1 - __bfloat162float(h01.y));
                __nv_bfloat162 l23 = __floats2bfloat162_rn(
                    p2 - __bfloat162float(h23.x), p3 - __bfloat162float(h23.y));
                pfh[kv][0 + 2 * half] = *(uint32_t*)&h01;
                pfh[kv][1 + 2 * half] = *(uint32_t*)&h23;
                pfl[kv][0 + 2 * half] = *(uint32_t*)&l01;
                pfl[kv][1 + 2 * half] = *(uint32_t*)&l23;
            }
        }

        // ---- O += P V ----
#pragma unroll
        for (int dp = 0; dp < 8; dp++) {
#pragma unroll
            for (int kv = 0; kv < 4; kv++) {
                uint32_t ad = vB + (uint32_t)(dp * 16 * VSTR + kv * 16) * 2u;
                uint32_t vh[4], vl[4];
                LDSM4(vh, ad);
                LDSM4(vl, ad + (uint32_t)V_ELEMS * 2u);
                float* oc0 = Oacc[2 * dp];
                float* oc1 = Oacc[2 * dp + 1];
                mma_bf16(oc0, pfh[kv][0], pfh[kv][1], pfh[kv][2], pfh[kv][3], vl[0], vl[1]);
                mma_bf16(oc0, pfl[kv][0], pfl[kv][1], pfl[kv][2], pfl[kv][3], vh[0], vh[1]);
                mma_bf16(oc0, pfh[kv][0], pfh[kv][1], pfh[kv][2], pfh[kv][3], vh[0], vh[1]);
                mma_bf16(oc1, pfh[kv][0], pfh[kv][1], pfh[kv][2], pfh[kv][3], vl[2], vl[3]);
                mma_bf16(oc1, pfl[kv][0], pfl[kv][1], pfl[kv][2], pfl[kv][3], vh[2], vh[3]);
                mma_bf16(oc1, pfh[kv][0], pfh[kv][1], pfh[kv][2], pfh[kv][3], vh[2], vh[3]);
            }
        }
    }

    // ---- finalize: write bf16 hi/lo directly ----
    float liA = 1.0f / lA, liB = 1.0f / lB;
    const size_t rowA = (tokbase + qr + g) * D_MODEL + h * D_HEAD;
    const size_t rowB = (tokbase + qr + g + 8) * D_MODEL + h * D_HEAD;
#pragma unroll
    for (int d = 0; d < 16; d++) {
        float a0 = Oacc[d][0] * liA, a1 = Oacc[d][1] * liA;
        float b0 = Oacc[d][2] * liB, b1 = Oacc[d][3] * liB;
        __nv_bfloat162 hA = __floats2bfloat162_rn(a0, a1);
        __nv_bfloat162 lAv = __floats2bfloat162_rn(a0 - __bfloat162float(hA.x),
                                                   a1 - __bfloat162float(hA.y));
        __nv_bfloat162 hB = __floats2bfloat162_rn(b0, b1);
        __nv_bfloat162 lBv = __floats2bfloat162_rn(b0 - __bfloat162float(hB.x),
                                                   b1 - __bfloat162float(hB.y));
        *(__nv_bfloat162*)(Oh + rowA + d * 8 + 2 * tg) = hA;
        *(__nv_bfloat162*)(Ol + rowA + d * 8 + 2 * tg) = lAv;
        *(__nv_bfloat162*)(Oh + rowB + d * 8 + 2 * tg) = hB;
        *(__nv_bfloat162*)(Ol + rowB + d * 8 + 2 * tg) = lBv;
    }
#undef ALOAD
}

// ---------------- host launch ----------------
extern "C" void kernel_launch(void* const* d_in, const int* in_sizes, int n_in,
                              void* d_out, int out_size)
{
    const float* x   = (const float*)d_in[0];
    const float* cosb= (const float*)d_in[1];
    const float* sinb= (const float*)d_in[2];
    const float* Wq  = (const float*)d_in[3];
    const float* bq  = (const float*)d_in[4];
    const float* Wk  = (const float*)d_in[5];
    const float* bk  = (const float*)d_in[6];
    const float* Wv  = (const float*)d_in[7];
    const float* bv  = (const float*)d_in[8];
    const float* qnw = (const float*)d_in[9];
    const float* knw = (const float*)d_in[10];
    const float* Wo  = (const float*)d_in[11];
    const float* bo  = (const float*)d_in[12];
    float* out = (float*)d_out;

    const int BT = in_sizes[0] / D_MODEL;    // 4096
    const int Bb = BT / T_SEQ;               // 2

    float *qp, *kp, *vp;
    cudaGetSymbolAddress((void**)&qp, g_q);
    cudaGetSymbolAddress((void**)&kp, g_k);
    cudaGetSymbolAddress((void**)&vp, g_v);
    __nv_bfloat16 *xh, *xl, *wh, *wl, *ah, *al, *qh, *ql, *kh, *kl, *vth, *vtl;
    cudaGetSymbolAddress((void**)&xh, g_xh);
    cudaGetSymbolAddress((void**)&xl, g_xl);
    cudaGetSymbolAddress((void**)&wh, g_wh);
    cudaGetSymbolAddress((void**)&wl, g_wl);
    cudaGetSymbolAddress((void**)&ah, g_ah);
    cudaGetSymbolAddress((void**)&al, g_al);
    cudaGetSymbolAddress((void**)&qh, g_qh);
    cudaGetSymbolAddress((void**)&ql, g_ql);
    cudaGetSymbolAddress((void**)&kh, g_kh);
    cudaGetSymbolAddress((void**)&kl, g_kl);
    cudaGetSymbolAddress((void**)&vth, g_vth);
    cudaGetSymbolAddress((void**)&vtl, g_vtl);

    cudaFuncSetAttribute(gemm_bf16, cudaFuncAttributeMaxDynamicSharedMemorySize, GEMM_SMEM);
    cudaFuncSetAttribute(attn_tc, cudaFuncAttributeMaxDynamicSharedMemorySize, ATTN_SMEM);

    const int nX4 = BT * D_MODEL / 4;
    const int nW4 = D_MODEL * D_MODEL / 4;
    const size_t woff = (size_t)D_MODEL * D_MODEL;

    split_bf16<<<(nX4 + 255) / 256, 256>>>(x, xh, xl, nX4);
    split_bf16<<<(nW4 + 255) / 256, 256>>>(Wq, wh + 0 * woff, wl + 0 * woff, nW4);
    split_bf16<<<(nW4 + 255) / 256, 256>>>(Wk, wh + 1 * woff, wl + 1 * woff, nW4);
    split_bf16<<<(nW4 + 255) / 256, 256>>>(Wv, wh + 2 * woff, wl + 2 * woff, nW4);
    split_bf16<<<(nW4 + 255) / 256, 256>>>(Wo, wh + 3 * woff, wl + 3 * woff, nW4);

    dim3 gq(D_MODEL / TN, BT / TM, 3);
    gemm_bf16<<<gq, 256, GEMM_SMEM>>>(xh, xl, wh, wl,
                                      bq, qp, bk, kp, bv, vp,
                                      BT, D_MODEL, D_MODEL);

    const float qscale = 0.08838834764831845f * 1.4426950408889634f;
    rmsnorm_rope_bf<<<BT, 256>>>(qp, qnw, cosb, sinb, qh, ql, qscale);
    rmsnorm_rope_bf<<<BT, 256>>>(kp, knw, cosb, sinb, kh, kl, 1.0f);

    dim3 vt(T_SEQ / 32, N_HEADS, Bb);
    split_transpose_v<<<vt, 256>>>(vp, vth, vtl);

    dim3 adim(T_SEQ / AQ, N_HEADS, Bb);
    attn_tc<<<adim, 256, ATTN_SMEM>>>(qh, ql, kh, kl, vth, vtl, ah, al);

    dim3 go(D_MODEL / TN, BT / TM, 1);
    gemm_bf16<<<go, 256, GEMM_SMEM>>>(ah, al, wh + 3 * woff, wl + 3 * woff,
                                      bo, out, bo, out, bo, out,
                                      BT, D_MODEL, D_MODEL);
}

// round 8
// speedup vs baseline: 3.3172x; 1.1115x over previous
#include <cuda_runtime.h>
#include <cuda_bf16.h>
#include <cstdint>
#include <math.h>

#define D_MODEL 2048
#define T_SEQ   2048
#define N_HEADS 16
#define D_HEAD  128
#define BT_MAX  4096   // B=2 * T=2048

// ---------------- scratch (device globals; allocation-free) ----------------
__device__ float g_q[(size_t)BT_MAX * D_MODEL];
__device__ float g_k[(size_t)BT_MAX * D_MODEL];
__device__ float g_v[(size_t)BT_MAX * D_MODEL];

__device__ __nv_bfloat16 g_xh[(size_t)BT_MAX * D_MODEL];
__device__ __nv_bfloat16 g_xl[(size_t)BT_MAX * D_MODEL];
__device__ __nv_bfloat16 g_wh[(size_t)4 * D_MODEL * D_MODEL];  // Wq,Wk,Wv,Wo hi
__device__ __nv_bfloat16 g_wl[(size_t)4 * D_MODEL * D_MODEL];  // lo
__device__ __nv_bfloat16 g_ah[(size_t)BT_MAX * D_MODEL];       // attn out hi
__device__ __nv_bfloat16 g_al[(size_t)BT_MAX * D_MODEL];

__device__ __nv_bfloat16 g_qh[(size_t)BT_MAX * D_MODEL];       // Q hi (scaled)
__device__ __nv_bfloat16 g_ql[(size_t)BT_MAX * D_MODEL];
__device__ __nv_bfloat16 g_kh[(size_t)BT_MAX * D_MODEL];       // K hi
__device__ __nv_bfloat16 g_kl[(size_t)BT_MAX * D_MODEL];
__device__ __nv_bfloat16 g_vth[(size_t)BT_MAX * D_MODEL];      // V^T hi [b,h,d,t]
__device__ __nv_bfloat16 g_vtl[(size_t)BT_MAX * D_MODEL];

__device__ __forceinline__ uint32_t smem_u32(const void* p) {
    uint32_t a;
    asm("{ .reg .u64 t; cvta.to.shared.u64 t, %1; cvt.u32.u64 %0, t; }" : "=r"(a) : "l"(p));
    return a;
}

__device__ __forceinline__ void mma_bf16(float* c, uint32_t a0, uint32_t a1,
                                         uint32_t a2, uint32_t a3,
                                         uint32_t b0, uint32_t b1) {
    asm volatile(
        "mma.sync.aligned.m16n8k16.row.col.f32.bf16.bf16.f32 "
        "{%0,%1,%2,%3}, {%4,%5,%6,%7}, {%8,%9}, {%0,%1,%2,%3};"
        : "+f"(c[0]), "+f"(c[1]), "+f"(c[2]), "+f"(c[3])
        : "r"(a0), "r"(a1), "r"(a2), "r"(a3), "r"(b0), "r"(b1));
}

#define LDSM4(r, a) asm volatile(                                                  \
    "ldmatrix.sync.aligned.m8n8.x4.shared.b16 {%0,%1,%2,%3}, [%4];"                \
    : "=r"((r)[0]), "=r"((r)[1]), "=r"((r)[2]), "=r"((r)[3]) : "r"(a))

__device__ __forceinline__ float ex2f(float x) {
    float r;
    asm("ex2.approx.f32 %0, %1;" : "=f"(r) : "f"(x));
    return r;
}

// ---------------- split fp32 -> bf16 hi + bf16 lo ----------------
__global__ __launch_bounds__(256) void split_bf16(
    const float* __restrict__ src, __nv_bfloat16* __restrict__ hi,
    __nv_bfloat16* __restrict__ lo, int n4)
{
    int i = blockIdx.x * 256 + threadIdx.x;
    if (i >= n4) return;
    float4 v = ((const float4*)src)[i];
    __nv_bfloat16 h0 = __float2bfloat16(v.x);
    __nv_bfloat16 h1 = __float2bfloat16(v.y);
    __nv_bfloat16 h2 = __float2bfloat16(v.z);
    __nv_bfloat16 h3 = __float2bfloat16(v.w);
    __nv_bfloat16 l0 = __float2bfloat16(v.x - __bfloat162float(h0));
    __nv_bfloat16 l1 = __float2bfloat16(v.y - __bfloat162float(h1));
    __nv_bfloat16 l2 = __float2bfloat16(v.z - __bfloat162float(h2));
    __nv_bfloat16 l3 = __float2bfloat16(v.w - __bfloat162float(h3));
    __nv_bfloat162* hp = (__nv_bfloat162*)(hi + (size_t)i * 4);
    __nv_bfloat162* lp = (__nv_bfloat162*)(lo + (size_t)i * 4);
    hp[0] = __nv_bfloat162(h0, h1); hp[1] = __nv_bfloat162(h2, h3);
    lp[0] = __nv_bfloat162(l0, l1); lp[1] = __nv_bfloat162(l2, l3);
}

// merged weight split: blockIdx.y selects which W
__global__ __launch_bounds__(256) void split_bf16_w(
    const float* __restrict__ w0, const float* __restrict__ w1,
    const float* __restrict__ w2, const float* __restrict__ w3,
    __nv_bfloat16* __restrict__ hi, __nv_bfloat16* __restrict__ lo, int n4)
{
    int i = blockIdx.x * 256 + threadIdx.x;
    if (i >= n4) return;
    int y = blockIdx.y;
    const float* src = (y == 0) ? w0 : (y == 1) ? w1 : (y == 2) ? w2 : w3;
    size_t off = (size_t)y * n4;
    float4 v = ((const float4*)src)[i];
    __nv_bfloat16 h0 = __float2bfloat16(v.x);
    __nv_bfloat16 h1 = __float2bfloat16(v.y);
    __nv_bfloat16 h2 = __float2bfloat16(v.z);
    __nv_bfloat16 h3 = __float2bfloat16(v.w);
    __nv_bfloat16 l0 = __float2bfloat16(v.x - __bfloat162float(h0));
    __nv_bfloat16 l1 = __float2bfloat16(v.y - __bfloat162float(h1));
    __nv_bfloat16 l2 = __float2bfloat16(v.z - __bfloat162float(h2));
    __nv_bfloat16 l3 = __float2bfloat16(v.w - __bfloat162float(h3));
    __nv_bfloat162* hp = (__nv_bfloat162*)(hi + (off + i) * 4);
    __nv_bfloat162* lp = (__nv_bfloat162*)(lo + (off + i) * 4);
    hp[0] = __nv_bfloat162(h0, h1); hp[1] = __nv_bfloat162(h2, h3);
    lp[0] = __nv_bfloat162(l0, l1); lp[1] = __nv_bfloat162(l2, l3);
}

// ---------------- split + transpose V ----------------
__global__ __launch_bounds__(256) void split_transpose_v(
    const float* __restrict__ V, __nv_bfloat16* __restrict__ vh,
    __nv_bfloat16* __restrict__ vl)
{
    __shared__ float tile[D_HEAD][33];
    const int t0 = blockIdx.x * 32;
    const int hh = blockIdx.y, b = blockIdx.z;
    const int tid = threadIdx.x;
    for (int i = tid; i < 32 * D_HEAD; i += 256) {
        int t = i >> 7, d = i & 127;
        tile[d][t] = V[((size_t)(b * T_SEQ + t0 + t)) * D_MODEL + hh * D_HEAD + d];
    }
    __syncthreads();
    for (int i = tid; i < 32 * D_HEAD; i += 256) {
        int d = i >> 5, t = i & 31;
        float v = tile[d][t];
        __nv_bfloat16 h = __float2bfloat16(v);
        __nv_bfloat16 l = __float2bfloat16(v - __bfloat162float(h));
        size_t o = ((size_t)((b * N_HEADS + hh) * D_HEAD + d)) * T_SEQ + t0 + t;
        vh[o] = h; vl[o] = l;
    }
}

// ---------------- 3xBF16 GEMM, CTA 128x256, warp tile 64x64 ----------------
#define TM 128
#define TN 256
#define TKF 32
#define BSTR 40
#define A_REG (TM * BSTR)              // 5120
#define B_REG (TN * BSTR)              // 10240
#define STAGE_E (2 * A_REG + 2 * B_REG)  // 30720 elems
#define GSTAGES 3
#define GEMM_SMEM (GSTAGES * STAGE_E * 2)  // 184320 B

__global__ __launch_bounds__(256) void gemm_bf16(
    const __nv_bfloat16* __restrict__ Ah, const __nv_bfloat16* __restrict__ Al,
    const __nv_bfloat16* __restrict__ Wh, const __nv_bfloat16* __restrict__ Wl,
    const float* __restrict__ bias0, float* __restrict__ C0,
    const float* __restrict__ bias1, float* __restrict__ C1,
    const float* __restrict__ bias2, float* __restrict__ C2,
    int M, int N, int K)
{
    extern __shared__ __nv_bfloat16 smem[];
    const int tid = threadIdx.x;
    const int bz = blockIdx.z;
    const __nv_bfloat16* Bh = Wh + (size_t)bz * D_MODEL * D_MODEL;
    const __nv_bfloat16* Bl = Wl + (size_t)bz * D_MODEL * D_MODEL;
    const float* bia = (bz == 0) ? bias0 : (bz == 1) ? bias1 : bias2;
    float*       C   = (bz == 0) ? C0 : (bz == 1) ? C1 : C2;

    const int m0 = blockIdx.y * TM;
    const int n0 = blockIdx.x * TN;
    const int NTILES = K / TKF;   // 64

    const uint32_t sbase = smem_u32(smem);

    // ---- load mapping: 3072 16B-chunks per stage, 12 per thread ----
    const __nv_bfloat16* gsrc[12];
    uint32_t soff[12];
#pragma unroll
    for (int i = 0; i < 12; i++) {
        int c = tid + i * 256;
        if (c < 1024) {
            int m = c & 511, row = m >> 2, j = m & 3;
            const __nv_bfloat16* bp = (c < 512) ? Ah : Al;
            gsrc[i] = bp + (size_t)(m0 + row) * K + j * 8;
            soff[i] = (uint32_t)(((c < 512) ? 0 : A_REG) + row * BSTR + j * 8) * 2u;
        } else {
            int cb = c - 1024;
            int m = cb & 1023, row = m >> 2, j = m & 3;
            const __nv_bfloat16* bp = (cb < 1024) ? Bh : Bl;
            gsrc[i] = bp + (size_t)(n0 + row) * K + j * 8;
            soff[i] = (uint32_t)(2 * A_REG + ((cb < 1024) ? 0 : B_REG)
                     + row * BSTR + j * 8) * 2u;
        }
    }

#define LOAD_TILE(t, s) do {                                                     \
        uint32_t _sb = sbase + (uint32_t)((s) * STAGE_E) * 2u;                   \
        size_t _go = (size_t)(t) * TKF;                                          \
        _Pragma("unroll")                                                        \
        for (int _i = 0; _i < 12; _i++) {                                        \
            asm volatile("cp.async.cg.shared.global [%0], [%1], 16;"             \
                :: "r"(_sb + soff[_i]), "l"(gsrc[_i] + _go));                    \
        } } while (0)

    const int warp = tid >> 5, lane = tid & 31;
    const int wm = (warp >> 2) * 64, wn = (warp & 3) * 64;
    const int g = lane >> 2, tg = lane & 3;

    // ldmatrix lane bases (bytes within a stage)
    const uint32_t aLane = (uint32_t)((wm + (lane & 15)) * BSTR + (lane >> 4) * 8) * 2u;
    const int bnrow = wn + (lane & 7) + ((lane & 16) ? 8 : 0);
    const uint32_t bLane = (uint32_t)(2 * A_REG + bnrow * BSTR + ((lane & 8) ? 8 : 0)) * 2u;

    float c[4][8][4];
#pragma unroll
    for (int mi = 0; mi < 4; mi++)
#pragma unroll
        for (int ni = 0; ni < 8; ni++)
#pragma unroll
            for (int r = 0; r < 4; r++) c[mi][ni][r] = 0.f;

    LOAD_TILE(0, 0);
    asm volatile("cp.async.commit_group;" ::: "memory");
    LOAD_TILE(1, 1);
    asm volatile("cp.async.commit_group;" ::: "memory");

    for (int kt = 0; kt < NTILES; kt++) {
        asm volatile("cp.async.wait_group 1;" ::: "memory");
        __syncthreads();

        int lt = kt + 2;
        if (lt < NTILES) LOAD_TILE(lt, lt % GSTAGES);
        asm volatile("cp.async.commit_group;" ::: "memory");

        const uint32_t stb = sbase + (uint32_t)((kt % GSTAGES) * STAGE_E) * 2u;
        const uint32_t aB = stb + aLane;
        const uint32_t bB = stb + bLane;

#pragma unroll
        for (int ks = 0; ks < 2; ks++) {
            uint32_t ah[4][4], al[4][4];
#pragma unroll
            for (int mi = 0; mi < 4; mi++) {
                uint32_t ad = aB + (uint32_t)(mi * 16 * BSTR + ks * 16) * 2u;
                LDSM4(ah[mi], ad);
                LDSM4(al[mi], ad + (uint32_t)A_REG * 2u);
            }
#pragma unroll
            for (int p = 0; p < 4; p++) {
                uint32_t bd = bB + (uint32_t)(p * 16 * BSTR + ks * 16) * 2u;
                uint32_t bh[4], bl[4];
                LDSM4(bh, bd);
                LDSM4(bl, bd + (uint32_t)B_REG * 2u);
#pragma unroll
                for (int mi = 0; mi < 4; mi++) {
#pragma unroll
                    for (int hf = 0; hf < 2; hf++) {
                        float* cc = c[mi][2 * p + hf];
                        mma_bf16(cc, ah[mi][0], ah[mi][1], ah[mi][2], ah[mi][3],
                                 bl[2 * hf], bl[2 * hf + 1]);
                        mma_bf16(cc, al[mi][0], al[mi][1], al[mi][2], al[mi][3],
                                 bh[2 * hf], bh[2 * hf + 1]);
                        mma_bf16(cc, ah[mi][0], ah[mi][1], ah[mi][2], ah[mi][3],
                                 bh[2 * hf], bh[2 * hf + 1]);
                    }
                }
            }
        }
    }

    // ---- epilogue: bias + store ----
#pragma unroll
    for (int ni = 0; ni < 8; ni++) {
        int col = n0 + wn + ni * 8 + 2 * tg;
        float2 bb = *(const float2*)(bia + col);
#pragma unroll
        for (int mi = 0; mi < 4; mi++) {
            int row = m0 + wm + mi * 16 + g;
            float2 o0, o1;
            o0.x = c[mi][ni][0] + bb.x; o0.y = c[mi][ni][1] + bb.y;
            o1.x = c[mi][ni][2] + bb.x; o1.y = c[mi][ni][3] + bb.y;
            *(float2*)(C + (size_t)row * N + col) = o0;
            *(float2*)(C + (size_t)(row + 8) * N + col) = o1;
        }
    }
#undef LOAD_TILE
}

// ---------------- fused RMSNorm + RoPE -> bf16 hi/lo; blockIdx.y: 0=Q, 1=K ----------------
__global__ __launch_bounds__(256) void rmsnorm_rope_bf(
    const float* __restrict__ qsrc, const float* __restrict__ ksrc,
    const float* __restrict__ qw, const float* __restrict__ kw,
    const float* __restrict__ cosb, const float* __restrict__ sinb,
    __nv_bfloat16* __restrict__ qoh, __nv_bfloat16* __restrict__ qol,
    __nv_bfloat16* __restrict__ koh, __nv_bfloat16* __restrict__ kol,
    float qscale)
{
    const int which = blockIdx.y;
    const float* hsrc = which ? ksrc : qsrc;
    const float* w    = which ? kw   : qw;
    __nv_bfloat16* oh = which ? koh  : qoh;
    __nv_bfloat16* ol = which ? kol  : qol;
    const float outscale = which ? 1.0f : qscale;

    const int row = blockIdx.x;
    const int t = row & (T_SEQ - 1);
    const float* hp = hsrc + (size_t)row * D_MODEL;
    const float* cp = cosb + (size_t)t * D_MODEL;
    const float* sp = sinb + (size_t)t * D_MODEL;
    const int tid = threadIdx.x;

    float4 vals[2];
    float ss = 0.f;
#pragma unroll
    for (int i = 0; i < 2; i++) {
        float4 v = ((const float4*)hp)[tid + i * 256];
        vals[i] = v;
        ss += v.x * v.x + v.y * v.y + v.z * v.z + v.w * v.w;
    }
#pragma unroll
    for (int o = 16; o > 0; o >>= 1) ss += __shfl_xor_sync(0xffffffffu, ss, o);
    __shared__ float red[8];
    __shared__ float s_inv;
    if ((tid & 31) == 0) red[tid >> 5] = ss;
    __syncthreads();
    if (tid == 0) {
        float tot = 0.f;
#pragma unroll
        for (int i = 0; i < 8; i++) tot += red[i];
        s_inv = rsqrtf(tot * (1.0f / D_MODEL) + 1e-6f);
    }
    __syncthreads();
    const float inv = s_inv;

#pragma unroll
    for (int i = 0; i < 2; i++) {
        int fi = tid + i * 256;
        float4 v = vals[i];
        float4 wv = ((const float4*)w)[fi];
        float4 c4 = ((const float4*)cp)[fi];
        float4 s4 = ((const float4*)sp)[fi];
        float nx = v.x * inv * wv.x;
        float ny = v.y * inv * wv.y;
        float nz = v.z * inv * wv.z;
        float nw = v.w * inv * wv.w;
        float o0 = (nx * c4.x - ny * s4.x) * outscale;
        float o1 = (ny * c4.y + nx * s4.y) * outscale;
        float o2 = (nz * c4.z - nw * s4.z) * outscale;
        float o3 = (nw * c4.w + nz * s4.w) * outscale;
        __nv_bfloat16 h0 = __float2bfloat16(o0), h1 = __float2bfloat16(o1);
        __nv_bfloat16 h2 = __float2bfloat16(o2), h3 = __float2bfloat16(o3);
        __nv_bfloat16 l0 = __float2bfloat16(o0 - __bfloat162float(h0));
        __nv_bfloat16 l1 = __float2bfloat16(o1 - __bfloat162float(h1));
        __nv_bfloat16 l2 = __float2bfloat16(o2 - __bfloat162float(h2));
        __nv_bfloat16 l3 = __float2bfloat16(o3 - __bfloat162float(h3));
        __nv_bfloat162* hp2 = (__nv_bfloat162*)(oh + (size_t)row * D_MODEL + fi * 4);
        __nv_bfloat162* lp2 = (__nv_bfloat162*)(ol + (size_t)row * D_MODEL + fi * 4);
        hp2[0] = __nv_bfloat162(h0, h1); hp2[1] = __nv_bfloat162(h2, h3);
        lp2[0] = __nv_bfloat162(l0, l1); lp2[1] = __nv_bfloat162(l2, l3);
    }
}

// ---------------- tensor-core flash attention (3xBF16, ldmatrix) ----------------
#define AQ 128
#define AK 64
#define KSTR 136
#define VSTR 72
#define K_ELEMS (AK * KSTR)
#define V_ELEMS (D_HEAD * VSTR)
#define ASTAGE (2 * K_ELEMS + 2 * V_ELEMS)
#define ATTN_SMEM (2 * ASTAGE * 2)

__global__ __launch_bounds__(256) void attn_tc(
    const __nv_bfloat16* __restrict__ Qh, const __nv_bfloat16* __restrict__ Ql,
    const __nv_bfloat16* __restrict__ Kh, const __nv_bfloat16* __restrict__ Kl,
    const __nv_bfloat16* __restrict__ Vth, const __nv_bfloat16* __restrict__ Vtl,
    __nv_bfloat16* __restrict__ Oh, __nv_bfloat16* __restrict__ Ol)
{
    extern __shared__ __nv_bfloat16 asm_s[];
    const int tid = threadIdx.x, warp = tid >> 5, lane = tid & 31;
    const int g = lane >> 2, tg = lane & 3;
    const int h = blockIdx.y, b = blockIdx.z;
    const int q0 = blockIdx.x * AQ;
    const size_t tokbase = (size_t)b * T_SEQ;
    const uint32_t sbase = smem_u32(asm_s);
    const int NT = T_SEQ / AK;

    const int lrow16 = (lane & 7) + ((lane & 16) ? 8 : 0);
    const int lkh = (lane & 8) ? 8 : 0;
    const uint32_t kLane = (uint32_t)(lrow16 * KSTR + lkh) * 2u;
    const uint32_t vLane = (uint32_t)(lrow16 * VSTR + lkh) * 2u + (uint32_t)(2 * K_ELEMS) * 2u;

    const int qr = q0 + warp * 16;
    uint32_t qfh[8][4], qfl[8][4];
    {
        const __nv_bfloat16* bh_ = Qh + (tokbase + qr) * D_MODEL + h * D_HEAD;
        const __nv_bfloat16* bl_ = Ql + (tokbase + qr) * D_MODEL + h * D_HEAD;
#pragma unroll
        for (int ks = 0; ks < 8; ks++) {
            int k0 = ks * 16 + 2 * tg;
            qfh[ks][0] = *(const uint32_t*)(bh_ + (size_t)g * D_MODEL + k0);
            qfh[ks][1] = *(const uint32_t*)(bh_ + (size_t)(g + 8) * D_MODEL + k0);
            qfh[ks][2] = *(const uint32_t*)(bh_ + (size_t)g * D_MODEL + k0 + 8);
            qfh[ks][3] = *(const uint32_t*)(bh_ + (size_t)(g + 8) * D_MODEL + k0 + 8);
            qfl[ks][0] = *(const uint32_t*)(bl_ + (size_t)g * D_MODEL + k0);
            qfl[ks][1] = *(const uint32_t*)(bl_ + (size_t)(g + 8) * D_MODEL + k0);
            qfl[ks][2] = *(const uint32_t*)(bl_ + (size_t)g * D_MODEL + k0 + 8);
            qfl[ks][3] = *(const uint32_t*)(bl_ + (size_t)(g + 8) * D_MODEL + k0 + 8);
        }
    }

    float Oacc[16][4];
#pragma unroll
    for (int d = 0; d < 16; d++)
#pragma unroll
        for (int r = 0; r < 4; r++) Oacc[d][r] = 0.f;
    float mA = -1e30f, mB = -1e30f, lA = 0.f, lB = 0.f;

#define ALOAD(kt, s) do {                                                            \
        uint32_t _sb = sbase + (uint32_t)(s) * (ASTAGE * 2);                         \
        _Pragma("unroll")                                                            \
        for (int _i = 0; _i < 16; _i++) {                                            \
            int _c = tid + _i * 256;                                                 \
            const __nv_bfloat16* _src; uint32_t _dst;                                \
            if (_c < 2048) {                                                         \
                int _m = _c & 1023; int _row = _m >> 4, _j = _m & 15;                \
                const __nv_bfloat16* _bp = (_c < 1024) ? Kh : Kl;                    \
                _src = _bp + (tokbase + (size_t)(kt) * AK + _row) * D_MODEL          \
                       + h * D_HEAD + _j * 8;                                        \
                _dst = _sb + (uint32_t)(((_c < 1024) ? 0 : K_ELEMS)                  \
                       + _row * KSTR + _j * 8) * 2u;                                 \
            } else {                                                                 \
                int _m = (_c - 2048) & 1023; int _d = _m >> 3, _j = _m & 7;          \
                const __nv_bfloat16* _bp = (_c < 3072) ? Vth : Vtl;                  \
                _src = _bp + ((size_t)((b * N_HEADS + h) * D_HEAD + _d)) * T_SEQ     \
                       + (size_t)(kt) * AK + _j * 8;                                 \
                _dst = _sb + (uint32_t)(2 * K_ELEMS + ((_c < 3072) ? 0 : V_ELEMS)    \
                       + _d * VSTR + _j * 8) * 2u;                                   \
            }                                                                        \
            asm volatile("cp.async.cg.shared.global [%0], [%1], 16;"                 \
                         :: "r"(_dst), "l"(_src));                                   \
        } } while (0)

    ALOAD(0, 0);
    asm volatile("cp.async.commit_group;" ::: "memory");

    for (int kt = 0; kt < NT; kt++) {
        __syncthreads();
        if (kt + 1 < NT) {
            ALOAD(kt + 1, (kt + 1) & 1);
            asm volatile("cp.async.commit_group;" ::: "memory");
            asm volatile("cp.async.wait_group 1;" ::: "memory");
        } else {
            asm volatile("cp.async.wait_group 0;" ::: "memory");
        }
        __syncthreads();

        const uint32_t stb = sbase + (uint32_t)((kt & 1) * ASTAGE) * 2u;
        const uint32_t kB = stb + kLane;
        const uint32_t vB = stb + vLane;

        float sf[8][4];
#pragma unroll
        for (int p = 0; p < 4; p++) {
            float acc0[4] = {0.f, 0.f, 0.f, 0.f};
            float acc1[4] = {0.f, 0.f, 0.f, 0.f};
#pragma unroll
            for (int ks = 0; ks < 8; ks++) {
                uint32_t ad = kB + (uint32_t)(p * 16 * KSTR + ks * 16) * 2u;
                uint32_t kh[4], kl[4];
                LDSM4(kh, ad);
                LDSM4(kl, ad + (uint32_t)K_ELEMS * 2u);
                mma_bf16(acc0, qfh[ks][0], qfh[ks][1], qfh[ks][2], qfh[ks][3], kl[0], kl[1]);
                mma_bf16(acc0, qfl[ks][0], qfl[ks][1], qfl[ks][2], qfl[ks][3], kh[0], kh[1]);
                mma_bf16(acc0, qfh[ks][0], qfh[ks][1], qfh[ks][2], qfh[ks][3], kh[0], kh[1]);
                mma_bf16(acc1, qfh[ks][0], qfh[ks][1], qfh[ks][2], qfh[ks][3], kl[2], kl[3]);
                mma_bf16(acc1, qfl[ks][0], qfl[ks][1], qfl[ks][2], qfl[ks][3], kh[2], kh[3]);
                mma_bf16(acc1, qfh[ks][0], qfh[ks][1], qfh[ks][2], qfh[ks][3], kh[2], kh[3]);
            }
#pragma unroll
            for (int r = 0; r < 4; r++) {
                sf[2 * p][r] = acc0[r];
                sf[2 * p + 1][r] = acc1[r];
            }
        }

        float tmA = fmaxf(sf[0][0], sf[0][1]);
        float tmB = fmaxf(sf[0][2], sf[0][3]);
#pragma unroll
        for (int n = 1; n < 8; n++) {
            tmA = fmaxf(tmA, fmaxf(sf[n][0], sf[n][1]));
            tmB = fmaxf(tmB, fmaxf(sf[n][2], sf[n][3]));
        }
        tmA = fmaxf(tmA, __shfl_xor_sync(0xffffffffu, tmA, 1));
        tmA = fmaxf(tmA, __shfl_xor_sync(0xffffffffu, tmA, 2));
        tmB = fmaxf(tmB, __shfl_xor_sync(0xffffffffu, tmB, 1));
        tmB = fmaxf(tmB, __shfl_xor_sync(0xffffffffu, tmB, 2));
        float mAn = fmaxf(mA, tmA), mBn = fmaxf(mB, tmB);
        float corrA = ex2f(mA - mAn), corrB = ex2f(mB - mBn);
        mA = mAn; mB = mBn;

        float sumA = 0.f, sumB = 0.f;
#pragma unroll
        for (int n = 0; n < 8; n++) {
            sf[n][0] = ex2f(sf[n][0] - mA);
            sf[n][1] = ex2f(sf[n][1] - mA);
            sf[n][2] = ex2f(sf[n][2] - mB);
            sf[n][3] = ex2f(sf[n][3] - mB);
            sumA += sf[n][0] + sf[n][1];
            sumB += sf[n][2] + sf[n][3];
        }
        sumA += __shfl_xor_sync(0xffffffffu, sumA, 1);
        sumA += __shfl_xor_sync(0xffffffffu, sumA, 2);
        sumB += __shfl_xor_sync(0xffffffffu, sumB, 1);
        sumB += __shfl_xor_sync(0xffffffffu, sumB, 2);
        lA = lA * corrA + sumA;
        lB = lB * corrB + sumB;

#pragma unroll
        for (int d = 0; d < 16; d++) {
            Oacc[d][0] *= corrA; Oacc[d][1] *= corrA;
            Oacc[d][2] *= corrB; Oacc[d][3] *= corrB;
        }

        uint32_t pfh[4][4], pfl[4][4];
#pragma unroll
        for (int kv = 0; kv < 4; kv++) {
#pragma unroll
            for (int half = 0; half < 2; half++) {
                int n = 2 * kv + half;
                float p0 = sf[n][0], p1 = sf[n][1], p2 = sf[n][2], p3 = sf[n][3];
                __nv_bfloat162 h01 = __floats2bfloat162_rn(p0, p1);
                __nv_bfloat162 h23 = __floats2bfloat162_rn(p2, p3);
                __nv_bfloat162 l01 = __floats2bfloat162_rn(
                    p0 - __bfloat162float(h01.x), p1 - __bfloat162float(h01.y));
                __nv_bfloat162 l23 = __floats2bfloat162_rn(
                    p2 - __bfloat162float(h23.x), p3 - __bfloat162float(h23.y));
                pfh[kv][0 + 2 * half] = *(uint32_t*)&h01;
                pfh[kv][1 + 2 * half] = *(uint32_t*)&h23;
                pfl[kv][0 + 2 * half] = *(uint32_t*)&l01;
                pfl[kv][1 + 2 * half] = *(uint32_t*)&l23;
            }
        }

#pragma unroll
        for (int dp = 0; dp < 8; dp++) {
#pragma unroll
            for (int kv = 0; kv < 4; kv++) {
                uint32_t ad = vB + (uint32_t)(dp * 16 * VSTR + kv * 16) * 2u;
                uint32_t vh[4], vl[4];
                LDSM4(vh, ad);
                LDSM4(vl, ad + (uint32_t)V_ELEMS * 2u);
                float* oc0 = Oacc[2 * dp];
                float* oc1 = Oacc[2 * dp + 1];
                mma_bf16(oc0, pfh[kv][0], pfh[kv][1], pfh[kv][2], pfh[kv][3], vl[0], vl[1]);
                mma_bf16(oc0, pfl[kv][0], pfl[kv][1], pfl[kv][2], pfl[kv][3], vh[0], vh[1]);
                mma_bf16(oc0, pfh[kv][0], pfh[kv][1], pfh[kv][2], pfh[kv][3], vh[0], vh[1]);
                mma_bf16(oc1, pfh[kv][0], pfh[kv][1], pfh[kv][2], pfh[kv][3], vl[2], vl[3]);
                mma_bf16(oc1, pfl[kv][0], pfl[kv][1], pfl[kv][2], pfl[kv][3], vh[2], vh[3]);
                mma_bf16(oc1, pfh[kv][0], pfh[kv][1], pfh[kv][2], pfh[kv][3], vh[2], vh[3]);
            }
        }
    }

    float liA = 1.0f / lA, liB = 1.0f / lB;
    const size_t rowA = (tokbase + qr + g) * D_MODEL + h * D_HEAD;
    const size_t rowB = (tokbase + qr + g + 8) * D_MODEL + h * D_HEAD;
#pragma unroll
    for (int d = 0; d < 16; d++) {
        float a0 = Oacc[d][0] * liA, a1 = Oacc[d][1] * liA;
        float b0 = Oacc[d][2] * liB, b1 = Oacc[d][3] * liB;
        __nv_bfloat162 hA = __floats2bfloat162_rn(a0, a1);
        __nv_bfloat162 lAv = __floats2bfloat162_rn(a0 - __bfloat162float(hA.x),
                                                   a1 - __bfloat162float(hA.y));
        __nv_bfloat162 hB = __floats2bfloat162_rn(b0, b1);
        __nv_bfloat162 lBv = __floats2bfloat162_rn(b0 - __bfloat162float(hB.x),
                                                   b1 - __bfloat162float(hB.y));
        *(__nv_bfloat162*)(Oh + rowA + d * 8 + 2 * tg) = hA;
        *(__nv_bfloat162*)(Ol + rowA + d * 8 + 2 * tg) = lAv;
        *(__nv_bfloat162*)(Oh + rowB + d * 8 + 2 * tg) = hB;
        *(__nv_bfloat162*)(Ol + rowB + d * 8 + 2 * tg) = lBv;
    }
#undef ALOAD
}

// ---------------- host launch ----------------
extern "C" void kernel_launch(void* const* d_in, const int* in_sizes, int n_in,
                              void* d_out, int out_size)
{
    const float* x   = (const float*)d_in[0];
    const float* cosb= (const float*)d_in[1];
    const float* sinb= (const float*)d_in[2];
    const float* Wq  = (const float*)d_in[3];
    const float* bq  = (const float*)d_in[4];
    const float* Wk  = (const float*)d_in[5];
    const float* bk  = (const float*)d_in[6];
    const float* Wv  = (const float*)d_in[7];
    const float* bv  = (const float*)d_in[8];
    const float* qnw = (const float*)d_in[9];
    const float* knw = (const float*)d_in[10];
    const float* Wo  = (const float*)d_in[11];
    const float* bo  = (const float*)d_in[12];
    float* out = (float*)d_out;

    const int BT = in_sizes[0] / D_MODEL;    // 4096
    const int Bb = BT / T_SEQ;               // 2

    float *qp, *kp, *vp;
    cudaGetSymbolAddress((void**)&qp, g_q);
    cudaGetSymbolAddress((void**)&kp, g_k);
    cudaGetSymbolAddress((void**)&vp, g_v);
    __nv_bfloat16 *xh, *xl, *wh, *wl, *ah, *al, *qh, *ql, *kh, *kl, *vth, *vtl;
    cudaGetSymbolAddress((void**)&xh, g_xh);
    cudaGetSymbolAddress((void**)&xl, g_xl);
    cudaGetSymbolAddress((void**)&wh, g_wh);
    cudaGetSymbolAddress((void**)&wl, g_wl);
    cudaGetSymbolAddress((void**)&ah, g_ah);
    cudaGetSymbolAddress((void**)&al, g_al);
    cudaGetSymbolAddress((void**)&qh, g_qh);
    cudaGetSymbolAddress((void**)&ql, g_ql);
    cudaGetSymbolAddress((void**)&kh, g_kh);
    cudaGetSymbolAddress((void**)&kl, g_kl);
    cudaGetSymbolAddress((void**)&vth, g_vth);
    cudaGetSymbolAddress((void**)&vtl, g_vtl);

    cudaFuncSetAttribute(gemm_bf16, cudaFuncAttributeMaxDynamicSharedMemorySize, GEMM_SMEM);
    cudaFuncSetAttribute(attn_tc, cudaFuncAttributeMaxDynamicSharedMemorySize, ATTN_SMEM);

    const int nX4 = BT * D_MODEL / 4;
    const int nW4 = D_MODEL * D_MODEL / 4;
    const size_t woff = (size_t)D_MODEL * D_MODEL;

    split_bf16<<<(nX4 + 255) / 256, 256>>>(x, xh, xl, nX4);
    dim3 ws((nW4 + 255) / 256, 4);
    split_bf16_w<<<ws, 256>>>(Wq, Wk, Wv, Wo, wh, wl, nW4);

    dim3 gq(D_MODEL / TN, BT / TM, 3);   // (8, 32, 3)
    gemm_bf16<<<gq, 256, GEMM_SMEM>>>(xh, xl, wh, wl,
                                      bq, qp, bk, kp, bv, vp,
                                      BT, D_MODEL, D_MODEL);

    const float qscale = 0.08838834764831845f * 1.4426950408889634f;
    dim3 rn(BT, 2);
    rmsnorm_rope_bf<<<rn, 256>>>(qp, kp, qnw, knw, cosb, sinb,
                                 qh, ql, kh, kl, qscale);

    dim3 vt(T_SEQ / 32, N_HEADS, Bb);
    split_transpose_v<<<vt, 256>>>(vp, vth, vtl);

    dim3 adim(T_SEQ / AQ, N_HEADS, Bb);
    attn_tc<<<adim, 256, ATTN_SMEM>>>(qh, ql, kh, kl, vth, vtl, ah, al);

    dim3 go(D_MODEL / TN, BT / TM, 1);   // (8, 32, 1)
    gemm_bf16<<<go, 256, GEMM_SMEM>>>(ah, al, wh + 3 * woff, wl + 3 * woff,
                                      bo, out, bo, out, bo, out,
                                      BT, D_MODEL, D_MODEL);
}

// round 11
// speedup vs baseline: 3.3474x; 1.0091x over previous
#include <cuda_runtime.h>
#include <cuda_bf16.h>
#include <cstdint>
#include <math.h>

#define D_MODEL 2048
#define T_SEQ   2048
#define N_HEADS 16
#define D_HEAD  128
#define BT_MAX  4096   // B=2 * T=2048

// ---------------- scratch (device globals; allocation-free) ----------------
__device__ float g_q[(size_t)BT_MAX * D_MODEL];
__device__ float g_k[(size_t)BT_MAX * D_MODEL];

__device__ __nv_bfloat16 g_xh[(size_t)BT_MAX * D_MODEL];
__device__ __nv_bfloat16 g_xl[(size_t)BT_MAX * D_MODEL];
__device__ __nv_bfloat16 g_wh[(size_t)4 * D_MODEL * D_MODEL];  // Wq,Wk,Wv,Wo hi
__device__ __nv_bfloat16 g_wl[(size_t)4 * D_MODEL * D_MODEL];  // lo
__device__ __nv_bfloat16 g_ah[(size_t)BT_MAX * D_MODEL];       // attn out hi
__device__ __nv_bfloat16 g_al[(size_t)BT_MAX * D_MODEL];

__device__ __nv_bfloat16 g_qh[(size_t)BT_MAX * D_MODEL];       // Q hi (scaled)
__device__ __nv_bfloat16 g_ql[(size_t)BT_MAX * D_MODEL];
__device__ __nv_bfloat16 g_kh[(size_t)BT_MAX * D_MODEL];       // K hi
__device__ __nv_bfloat16 g_kl[(size_t)BT_MAX * D_MODEL];
__device__ __nv_bfloat16 g_vh[(size_t)BT_MAX * D_MODEL];       // V hi [b*t, 2048]
__device__ __nv_bfloat16 g_vl[(size_t)BT_MAX * D_MODEL];

__device__ __forceinline__ uint32_t smem_u32(const void* p) {
    uint32_t a;
    asm("{ .reg .u64 t; cvta.to.shared.u64 t, %1; cvt.u32.u64 %0, t; }" : "=r"(a) : "l"(p));
    return a;
}

__device__ __forceinline__ void mma_bf16(float* c, uint32_t a0, uint32_t a1,
                                         uint32_t a2, uint32_t a3,
                                         uint32_t b0, uint32_t b1) {
    asm volatile(
        "mma.sync.aligned.m16n8k16.row.col.f32.bf16.bf16.f32 "
        "{%0,%1,%2,%3}, {%4,%5,%6,%7}, {%8,%9}, {%0,%1,%2,%3};"
        : "+f"(c[0]), "+f"(c[1]), "+f"(c[2]), "+f"(c[3])
        : "r"(a0), "r"(a1), "r"(a2), "r"(a3), "r"(b0), "r"(b1));
}

#define LDSM4(r, a) asm volatile(                                                  \
    "ldmatrix.sync.aligned.m8n8.x4.shared.b16 {%0,%1,%2,%3}, [%4];"                \
    : "=r"((r)[0]), "=r"((r)[1]), "=r"((r)[2]), "=r"((r)[3]) : "r"(a))

#define LDSM4T(r, a) asm volatile(                                                 \
    "ldmatrix.sync.aligned.m8n8.x4.trans.shared.b16 {%0,%1,%2,%3}, [%4];"          \
    : "=r"((r)[0]), "=r"((r)[1]), "=r"((r)[2]), "=r"((r)[3]) : "r"(a))

__device__ __forceinline__ float ex2f(float x) {
    float r;
    asm("ex2.approx.f32 %0, %1;" : "=f"(r) : "f"(x));
    return r;
}

// ---------------- split fp32 -> bf16 hi + bf16 lo ----------------
__global__ __launch_bounds__(256) void split_bf16(
    const float* __restrict__ src, __nv_bfloat16* __restrict__ hi,
    __nv_bfloat16* __restrict__ lo, int n4)
{
    int i = blockIdx.x * 256 + threadIdx.x;
    if (i >= n4) return;
    float4 v = ((const float4*)src)[i];
    __nv_bfloat16 h0 = __float2bfloat16(v.x);
    __nv_bfloat16 h1 = __float2bfloat16(v.y);
    __nv_bfloat16 h2 = __float2bfloat16(v.z);
    __nv_bfloat16 h3 = __float2bfloat16(v.w);
    __nv_bfloat16 l0 = __float2bfloat16(v.x - __bfloat162float(h0));
    __nv_bfloat16 l1 = __float2bfloat16(v.y - __bfloat162float(h1));
    __nv_bfloat16 l2 = __float2bfloat16(v.z - __bfloat162float(h2));
    __nv_bfloat16 l3 = __float2bfloat16(v.w - __bfloat162float(h3));
    __nv_bfloat162* hp = (__nv_bfloat162*)(hi + (size_t)i * 4);
    __nv_bfloat162* lp = (__nv_bfloat162*)(lo + (size_t)i * 4);
    hp[0] = __nv_bfloat162(h0, h1); hp[1] = __nv_bfloat162(h2, h3);
    lp[0] = __nv_bfloat162(l0, l1); lp[1] = __nv_bfloat162(l2, l3);
}

// merged weight split: blockIdx.y selects which W
__global__ __launch_bounds__(256) void split_bf16_w(
    const float* __restrict__ w0, const float* __restrict__ w1,
    const float* __restrict__ w2, const float* __restrict__ w3,
    __nv_bfloat16* __restrict__ hi, __nv_bfloat16* __restrict__ lo, int n4)
{
    int i = blockIdx.x * 256 + threadIdx.x;
    if (i >= n4) return;
    int y = blockIdx.y;
    const float* src = (y == 0) ? w0 : (y == 1) ? w1 : (y == 2) ? w2 : w3;
    size_t off = (size_t)y * n4;
    float4 v = ((const float4*)src)[i];
    __nv_bfloat16 h0 = __float2bfloat16(v.x);
    __nv_bfloat16 h1 = __float2bfloat16(v.y);
    __nv_bfloat16 h2 = __float2bfloat16(v.z);
    __nv_bfloat16 h3 = __float2bfloat16(v.w);
    __nv_bfloat16 l0 = __float2bfloat16(v.x - __bfloat162float(h0));
    __nv_bfloat16 l1 = __float2bfloat16(v.y - __bfloat162float(h1));
    __nv_bfloat16 l2 = __float2bfloat16(v.z - __bfloat162float(h2));
    __nv_bfloat16 l3 = __float2bfloat16(v.w - __bfloat162float(h3));
    __nv_bfloat162* hp = (__nv_bfloat162*)(hi + (off + i) * 4);
    __nv_bfloat162* lp = (__nv_bfloat162*)(lo + (off + i) * 4);
    hp[0] = __nv_bfloat162(h0, h1); hp[1] = __nv_bfloat162(h2, h3);
    lp[0] = __nv_bfloat162(l0, l1); lp[1] = __nv_bfloat162(l2, l3);
}

// ---------------- 3xBF16 GEMM, CTA 128x256, warp tile 64x64 ----------------
// bz==2 writes bf16 hi/lo (V path); otherwise fp32.
#define TM 128
#define TN 256
#define TKF 32
#define BSTR 40
#define A_REG (TM * BSTR)              // 5120
#define B_REG (TN * BSTR)              // 10240
#define STAGE_E (2 * A_REG + 2 * B_REG)  // 30720 elems
#define GSTAGES 3
#define GEMM_SMEM (GSTAGES * STAGE_E * 2)  // 184320 B

__global__ __launch_bounds__(256) void gemm_bf16(
    const __nv_bfloat16* __restrict__ Ah, const __nv_bfloat16* __restrict__ Al,
    const __nv_bfloat16* __restrict__ Wh, const __nv_bfloat16* __restrict__ Wl,
    const float* __restrict__ bias0, float* __restrict__ C0,
    const float* __restrict__ bias1, float* __restrict__ C1,
    const float* __restrict__ bias2,
    __nv_bfloat16* __restrict__ Vh, __nv_bfloat16* __restrict__ Vl,
    int M, int N, int K)
{
    extern __shared__ __nv_bfloat16 smem[];
    const int tid = threadIdx.x;
    const int bz = blockIdx.z;
    const __nv_bfloat16* Bh = Wh + (size_t)bz * D_MODEL * D_MODEL;
    const __nv_bfloat16* Bl = Wl + (size_t)bz * D_MODEL * D_MODEL;
    const float* bia = (bz == 0) ? bias0 : (bz == 1) ? bias1 : bias2;
    float*       C   = (bz == 0) ? C0 : C1;

    const int m0 = blockIdx.y * TM;
    const int n0 = blockIdx.x * TN;
    const int NTILES = K / TKF;   // 64

    const uint32_t sbase = smem_u32(smem);

    // ---- load mapping: 3072 16B-chunks per stage, 12 per thread ----
    const __nv_bfloat16* gsrc[12];
    uint32_t soff[12];
#pragma unroll
    for (int i = 0; i < 12; i++) {
        int c = tid + i * 256;
        if (c < 1024) {
            int m = c & 511, row = m >> 2, j = m & 3;
            const __nv_bfloat16* bp = (c < 512) ? Ah : Al;
            gsrc[i] = bp + (size_t)(m0 + row) * K + j * 8;
            soff[i] = (uint32_t)(((c < 512) ? 0 : A_REG) + row * BSTR + j * 8) * 2u;
        } else {
            int cb = c - 1024;
            int m = cb & 1023, row = m >> 2, j = m & 3;
            const __nv_bfloat16* bp = (cb < 1024) ? Bh : Bl;
            gsrc[i] = bp + (size_t)(n0 + row) * K + j * 8;
            soff[i] = (uint32_t)(2 * A_REG + ((cb < 1024) ? 0 : B_REG)
                     + row * BSTR + j * 8) * 2u;
        }
    }

#define LOAD_TILE(t, s) do {                                                     \
        uint32_t _sb = sbase + (uint32_t)((s) * STAGE_E) * 2u;                   \
        size_t _go = (size_t)(t) * TKF;                                          \
        _Pragma("unroll")                                                        \
        for (int _i = 0; _i < 12; _i++) {                                        \
            asm volatile("cp.async.cg.shared.global [%0], [%1], 16;"             \
                :: "r"(_sb + soff[_i]), "l"(gsrc[_i] + _go));                    \
        } } while (0)

    const int warp = tid >> 5, lane = tid & 31;
    const int wm = (warp >> 2) * 64, wn = (warp & 3) * 64;
    const int g = lane >> 2, tg = lane & 3;

    const uint32_t aLane = (uint32_t)((wm + (lane & 15)) * BSTR + (lane >> 4) * 8) * 2u;
    const int bnrow = wn + (lane & 7) + ((lane & 16) ? 8 : 0);
    const uint32_t bLane = (uint32_t)(2 * A_REG + bnrow * BSTR + ((lane & 8) ? 8 : 0)) * 2u;

    float c[4][8][4];
#pragma unroll
    for (int mi = 0; mi < 4; mi++)
#pragma unroll
        for (int ni = 0; ni < 8; ni++)
#pragma unroll
            for (int r = 0; r < 4; r++) c[mi][ni][r] = 0.f;

    LOAD_TILE(0, 0);
    asm volatile("cp.async.commit_group;" ::: "memory");
    LOAD_TILE(1, 1);
    asm volatile("cp.async.commit_group;" ::: "memory");

    for (int kt = 0; kt < NTILES; kt++) {
        asm volatile("cp.async.wait_group 1;" ::: "memory");
        __syncthreads();

        int lt = kt + 2;
        if (lt < NTILES) LOAD_TILE(lt, lt % GSTAGES);
        asm volatile("cp.async.commit_group;" ::: "memory");

        const uint32_t stb = sbase + (uint32_t)((kt % GSTAGES) * STAGE_E) * 2u;
        const uint32_t aB = stb + aLane;
        const uint32_t bB = stb + bLane;

#pragma unroll
        for (int ks = 0; ks < 2; ks++) {
            uint32_t ah[4][4], al[4][4];
#pragma unroll
            for (int mi = 0; mi < 4; mi++) {
                uint32_t ad = aB + (uint32_t)(mi * 16 * BSTR + ks * 16) * 2u;
                LDSM4(ah[mi], ad);
                LDSM4(al[mi], ad + (uint32_t)A_REG * 2u);
            }
#pragma unroll
            for (int p = 0; p < 4; p++) {
                uint32_t bd = bB + (uint32_t)(p * 16 * BSTR + ks * 16) * 2u;
                uint32_t bh[4], bl[4];
                LDSM4(bh, bd);
                LDSM4(bl, bd + (uint32_t)B_REG * 2u);
#pragma unroll
                for (int mi = 0; mi < 4; mi++) {
#pragma unroll
                    for (int hf = 0; hf < 2; hf++) {
                        float* cc = c[mi][2 * p + hf];
                        mma_bf16(cc, ah[mi][0], ah[mi][1], ah[mi][2], ah[mi][3],
                                 bl[2 * hf], bl[2 * hf + 1]);
                        mma_bf16(cc, al[mi][0], al[mi][1], al[mi][2], al[mi][3],
                                 bh[2 * hf], bh[2 * hf + 1]);
                        mma_bf16(cc, ah[mi][0], ah[mi][1], ah[mi][2], ah[mi][3],
                                 bh[2 * hf], bh[2 * hf + 1]);
                    }
                }
            }
        }
    }

    // ---- epilogue ----
#pragma unroll
    for (int ni = 0; ni < 8; ni++) {
        int col = n0 + wn + ni * 8 + 2 * tg;
        float2 bb = *(const float2*)(bia + col);
#pragma unroll
        for (int mi = 0; mi < 4; mi++) {
            int row = m0 + wm + mi * 16 + g;
            float o00 = c[mi][ni][0] + bb.x, o01 = c[mi][ni][1] + bb.y;
            float o10 = c[mi][ni][2] + bb.x, o11 = c[mi][ni][3] + bb.y;
            if (bz == 2) {
                __nv_bfloat162 h0 = __floats2bfloat162_rn(o00, o01);
                __nv_bfloat162 l0 = __floats2bfloat162_rn(
                    o00 - __bfloat162float(h0.x), o01 - __bfloat162float(h0.y));
                __nv_bfloat162 h1 = __floats2bfloat162_rn(o10, o11);
                __nv_bfloat162 l1 = __floats2bfloat162_rn(
                    o10 - __bfloat162float(h1.x), o11 - __bfloat162float(h1.y));
                *(__nv_bfloat162*)(Vh + (size_t)row * N + col) = h0;
                *(__nv_bfloat162*)(Vl + (size_t)row * N + col) = l0;
                *(__nv_bfloat162*)(Vh + (size_t)(row + 8) * N + col) = h1;
                *(__nv_bfloat162*)(Vl + (size_t)(row + 8) * N + col) = l1;
            } else {
                float2 w0 = make_float2(o00, o01), w1 = make_float2(o10, o11);
                *(float2*)(C + (size_t)row * N + col) = w0;
                *(float2*)(C + (size_t)(row + 8) * N + col) = w1;
            }
        }
    }
#undef LOAD_TILE
}

// ---------------- fused RMSNorm + RoPE -> bf16 hi/lo; blockIdx.y: 0=Q, 1=K ----------------
__global__ __launch_bounds__(256) void rmsnorm_rope_bf(
    const float* __restrict__ qsrc, const float* __restrict__ ksrc,
    const float* __restrict__ qw, const float* __restrict__ kw,
    const float* __restrict__ cosb, const float* __restrict__ sinb,
    __nv_bfloat16* __restrict__ qoh, __nv_bfloat16* __restrict__ qol,
    __nv_bfloat16* __restrict__ koh, __nv_bfloat16* __restrict__ kol,
    float qscale)
{
    const int which = blockIdx.y;
    const float* hsrc = which ? ksrc : qsrc;
    const float* w    = which ? kw   : qw;
    __nv_bfloat16* oh = which ? koh  : qoh;
    __nv_bfloat16* ol = which ? kol  : qol;
    const float outscale = which ? 1.0f : qscale;

    const int row = blockIdx.x;
    const int t = row & (T_SEQ - 1);
    const float* hp = hsrc + (size_t)row * D_MODEL;
    const float* cp = cosb + (size_t)t * D_MODEL;
    const float* sp = sinb + (size_t)t * D_MODEL;
    const int tid = threadIdx.x;

    float4 vals[2];
    float ss = 0.f;
#pragma unroll
    for (int i = 0; i < 2; i++) {
        float4 v = ((const float4*)hp)[tid + i * 256];
        vals[i] = v;
        ss += v.x * v.x + v.y * v.y + v.z * v.z + v.w * v.w;
    }
#pragma unroll
    for (int o = 16; o > 0; o >>= 1) ss += __shfl_xor_sync(0xffffffffu, ss, o);
    __shared__ float red[8];
    __shared__ float s_inv;
    if ((tid & 31) == 0) red[tid >> 5] = ss;
    __syncthreads();
    if (tid == 0) {
        float tot = 0.f;
#pragma unroll
        for (int i = 0; i < 8; i++) tot += red[i];
        s_inv = rsqrtf(tot * (1.0f / D_MODEL) + 1e-6f);
    }
    __syncthreads();
    const float inv = s_inv;

#pragma unroll
    for (int i = 0; i < 2; i++) {
        int fi = tid + i * 256;
        float4 v = vals[i];
        float4 wv = ((const float4*)w)[fi];
        float4 c4 = ((const float4*)cp)[fi];
        float4 s4 = ((const float4*)sp)[fi];
        float nx = v.x * inv * wv.x;
        float ny = v.y * inv * wv.y;
        float nz = v.z * inv * wv.z;
        float nw = v.w * inv * wv.w;
        float o0 = (nx * c4.x - ny * s4.x) * outscale;
        float o1 = (ny * c4.y + nx * s4.y) * outscale;
        float o2 = (nz * c4.z - nw * s4.z) * outscale;
        float o3 = (nw * c4.w + nz * s4.w) * outscale;
        __nv_bfloat16 h0 = __float2bfloat16(o0), h1 = __float2bfloat16(o1);
        __nv_bfloat16 h2 = __float2bfloat16(o2), h3 = __float2bfloat16(o3);
        __nv_bfloat16 l0 = __float2bfloat16(o0 - __bfloat162float(h0));
        __nv_bfloat16 l1 = __float2bfloat16(o1 - __bfloat162float(h1));
        __nv_bfloat16 l2 = __float2bfloat16(o2 - __bfloat162float(h2));
        __nv_bfloat16 l3 = __float2bfloat16(o3 - __bfloat162float(h3));
        __nv_bfloat162* hp2 = (__nv_bfloat162*)(oh + (size_t)row * D_MODEL + fi * 4);
        __nv_bfloat162* lp2 = (__nv_bfloat162*)(ol + (size_t)row * D_MODEL + fi * 4);
        hp2[0] = __nv_bfloat162(h0, h1); hp2[1] = __nv_bfloat162(h2, h3);
        lp2[0] = __nv_bfloat162(l0, l1); lp2[1] = __nv_bfloat162(l2, l3);
    }
}

// ---------------- tensor-core flash attention (3xBF16, 2 CTAs/SM) ----------------
// AQ=64, 128 threads. K double-buffered, V single-buffered. V trans via ldmatrix.
#define AQ 64
#define AK 64
#define KSTR 136
#define K_ELEMS (AK * KSTR)                  // 8704
#define KSTAGE (2 * K_ELEMS)                 // hi+lo, 17408 elems
#define V_BASE (2 * KSTAGE)                  // after 2 K stages
#define ATTN_ELEMS (V_BASE + 2 * K_ELEMS)    // 52224 elems
#define ATTN_SMEM (ATTN_ELEMS * 2)           // 104448 B

__global__ __launch_bounds__(128, 2) void attn_tc(
    const __nv_bfloat16* __restrict__ Qh, const __nv_bfloat16* __restrict__ Ql,
    const __nv_bfloat16* __restrict__ Kh, const __nv_bfloat16* __restrict__ Kl,
    const __nv_bfloat16* __restrict__ Vh, const __nv_bfloat16* __restrict__ Vl,
    __nv_bfloat16* __restrict__ Oh, __nv_bfloat16* __restrict__ Ol)
{
    extern __shared__ __nv_bfloat16 asm_s[];
    const int tid = threadIdx.x, warp = tid >> 5, lane = tid & 31;
    const int g = lane >> 2, tg = lane & 3;
    const int h = blockIdx.y, b = blockIdx.z;
    const int q0 = blockIdx.x * AQ;
    const size_t tokbase = (size_t)b * T_SEQ;
    const uint32_t sbase = smem_u32(asm_s);
    const int NT = T_SEQ / AK;   // 32

    // K fragment lane base (non-trans): rows = token
    const int lrow16 = (lane & 7) + ((lane & 16) ? 8 : 0);
    const uint32_t kLane = (uint32_t)(lrow16 * KSTR + ((lane & 8) ? 8 : 0)) * 2u;
    // V fragment lane base (trans): rows = token (lane&15), col half by lane&16
    const uint32_t vLane = (uint32_t)((lane & 15) * KSTR + ((lane & 16) ? 8 : 0)) * 2u
                         + (uint32_t)V_BASE * 2u;

    // ---- Q fragments in registers (16 rows per warp) ----
    const int qr = q0 + warp * 16;
    uint32_t qfh[8][4], qfl[8][4];
    {
        const __nv_bfloat16* bh_ = Qh + (tokbase + qr) * D_MODEL + h * D_HEAD;
        const __nv_bfloat16* bl_ = Ql + (tokbase + qr) * D_MODEL + h * D_HEAD;
#pragma unroll
        for (int ks = 0; ks < 8; ks++) {
            int k0 = ks * 16 + 2 * tg;
            qfh[ks][0] = *(const uint32_t*)(bh_ + (size_t)g * D_MODEL + k0);
            qfh[ks][1] = *(const uint32_t*)(bh_ + (size_t)(g + 8) * D_MODEL + k0);
            qfh[ks][2] = *(const uint32_t*)(bh_ + (size_t)g * D_MODEL + k0 + 8);
            qfh[ks][3] = *(const uint32_t*)(bh_ + (size_t)(g + 8) * D_MODEL + k0 + 8);
            qfl[ks][0] = *(const uint32_t*)(bl_ + (size_t)g * D_MODEL + k0);
            qfl[ks][1] = *(const uint32_t*)(bl_ + (size_t)(g + 8) * D_MODEL + k0);
            qfl[ks][2] = *(const uint32_t*)(bl_ + (size_t)g * D_MODEL + k0 + 8);
            qfl[ks][3] = *(const uint32_t*)(bl_ + (size_t)(g + 8) * D_MODEL + k0 + 8);
        }
    }

    float Oacc[16][4];
#pragma unroll
    for (int d = 0; d < 16; d++)
#pragma unroll
        for (int r = 0; r < 4; r++) Oacc[d][r] = 0.f;
    float mA = -1e30f, mB = -1e30f, lA = 0.f, lB = 0.f;

    // 2048 chunks per K/V load, 16 per thread (128 threads)
#define LOAD_K(kt, s) do {                                                           \
        uint32_t _sb = sbase + (uint32_t)((s) * KSTAGE) * 2u;                        \
        _Pragma("unroll")                                                            \
        for (int _i = 0; _i < 16; _i++) {                                            \
            int _c = tid + _i * 128;                                                 \
            int _m = _c & 1023; int _row = _m >> 4, _j = _m & 15;                    \
            const __nv_bfloat16* _bp = (_c < 1024) ? Kh : Kl;                        \
            const __nv_bfloat16* _src = _bp + (tokbase + (size_t)(kt) * AK + _row)   \
                                        * D_MODEL + h * D_HEAD + _j * 8;             \
            uint32_t _dst = _sb + (uint32_t)(((_c < 1024) ? 0 : K_ELEMS)             \
                            + _row * KSTR + _j * 8) * 2u;                            \
            asm volatile("cp.async.cg.shared.global [%0], [%1], 16;"                 \
                         :: "r"(_dst), "l"(_src));                                   \
        } } while (0)

#define LOAD_V(kt) do {                                                              \
        uint32_t _sb = sbase + (uint32_t)V_BASE * 2u;                                \
        _Pragma("unroll")                                                            \
        for (int _i = 0; _i < 16; _i++) {                                            \
            int _c = tid + _i * 128;                                                 \
            int _m = _c & 1023; int _row = _m >> 4, _j = _m & 15;                    \
            const __nv_bfloat16* _bp = (_c < 1024) ? Vh : Vl;                        \
            const __nv_bfloat16* _src = _bp + (tokbase + (size_t)(kt) * AK + _row)   \
                                        * D_MODEL + h * D_HEAD + _j * 8;             \
            uint32_t _dst = _sb + (uint32_t)(((_c < 1024) ? 0 : K_ELEMS)             \
                            + _row * KSTR + _j * 8) * 2u;                            \
            asm volatile("cp.async.cg.shared.global [%0], [%1], 16;"                 \
                         :: "r"(_dst), "l"(_src));                                   \
        } } while (0)

    LOAD_K(0, 0);
    asm volatile("cp.async.commit_group;" ::: "memory");

    for (int kt = 0; kt < NT; kt++) {
        __syncthreads();   // all warps done with V buffer + K stage (kt+1)&1
        LOAD_V(kt);
        asm volatile("cp.async.commit_group;" ::: "memory");
        if (kt + 1 < NT) LOAD_K(kt + 1, (kt + 1) & 1);
        asm volatile("cp.async.commit_group;" ::: "memory");   // always (maybe empty)
        asm volatile("cp.async.wait_group 2;" ::: "memory");   // K(kt) ready
        __syncthreads();

        const uint32_t kB = sbase + (uint32_t)((kt & 1) * KSTAGE) * 2u + kLane;

        // ---- S = Q K^T (16 x 64 per warp) ----
        float sf[8][4];
#pragma unroll
        for (int p = 0; p < 4; p++) {
            float acc0[4] = {0.f, 0.f, 0.f, 0.f};
            float acc1[4] = {0.f, 0.f, 0.f, 0.f};
#pragma unroll
            for (int ks = 0; ks < 8; ks++) {
                uint32_t ad = kB + (uint32_t)(p * 16 * KSTR + ks * 16) * 2u;
                uint32_t kh[4], kl[4];
                LDSM4(kh, ad);
                LDSM4(kl, ad + (uint32_t)K_ELEMS * 2u);
                mma_bf16(acc0, qfh[ks][0], qfh[ks][1], qfh[ks][2], qfh[ks][3], kl[0], kl[1]);
                mma_bf16(acc0, qfl[ks][0], qfl[ks][1], qfl[ks][2], qfl[ks][3], kh[0], kh[1]);
                mma_bf16(acc0, qfh[ks][0], qfh[ks][1], qfh[ks][2], qfh[ks][3], kh[0], kh[1]);
                mma_bf16(acc1, qfh[ks][0], qfh[ks][1], qfh[ks][2], qfh[ks][3], kl[2], kl[3]);
                mma_bf16(acc1, qfl[ks][0], qfl[ks][1], qfl[ks][2], qfl[ks][3], kh[2], kh[3]);
                mma_bf16(acc1, qfh[ks][0], qfh[ks][1], qfh[ks][2], qfh[ks][3], kh[2], kh[3]);
            }
#pragma unroll
            for (int r = 0; r < 4; r++) {
                sf[2 * p][r] = acc0[r];
                sf[2 * p + 1][r] = acc1[r];
            }
        }

        // ---- online softmax (exp2 domain) ----
        float tmA = fmaxf(sf[0][0], sf[0][1]);
        float tmB = fmaxf(sf[0][2], sf[0][3]);
#pragma unroll
        for (int n = 1; n < 8; n++) {
            tmA = fmaxf(tmA, fmaxf(sf[n][0], sf[n][1]));
            tmB = fmaxf(tmB, fmaxf(sf[n][2], sf[n][3]));
        }
        tmA = fmaxf(tmA, __shfl_xor_sync(0xffffffffu, tmA, 1));
        tmA = fmaxf(tmA, __shfl_xor_sync(0xffffffffu, tmA, 2));
        tmB = fmaxf(tmB, __shfl_xor_sync(0xffffffffu, tmB, 1));
        tmB = fmaxf(tmB, __shfl_xor_sync(0xffffffffu, tmB, 2));
        float mAn = fmaxf(mA, tmA), mBn = fmaxf(mB, tmB);
        float corrA = ex2f(mA - mAn), corrB = ex2f(mB - mBn);
        mA = mAn; mB = mBn;

        float sumA = 0.f, sumB = 0.f;
#pragma unroll
        for (int n = 0; n < 8; n++) {
            sf[n][0] = ex2f(sf[n][0] - mA);
            sf[n][1] = ex2f(sf[n][1] - mA);
            sf[n][2] = ex2f(sf[n][2] - mB);
            sf[n][3] = ex2f(sf[n][3] - mB);
            sumA += sf[n][0] + sf[n][1];
            sumB += sf[n][2] + sf[n][3];
        }
        sumA += __shfl_xor_sync(0xffffffffu, sumA, 1);
        sumA += __shfl_xor_sync(0xffffffffu, sumA, 2);
        sumB += __shfl_xor_sync(0xffffffffu, sumB, 1);
        sumB += __shfl_xor_sync(0xffffffffu, sumB, 2);
        lA = lA * corrA + sumA;
        lB = lB * corrB + sumB;

#pragma unroll
        for (int d = 0; d < 16; d++) {
            Oacc[d][0] *= corrA; Oacc[d][1] *= corrA;
            Oacc[d][2] *= corrB; Oacc[d][3] *= corrB;
        }

        // ---- P fragments (hi/lo bf16) ----
        uint32_t pfh[4][4], pfl[4][4];
#pragma unroll
        for (int kv = 0; kv < 4; kv++) {
#pragma unroll
            for (int half = 0; half < 2; half++) {
                int n = 2 * kv + half;
                float p0 = sf[n][0], p1 = sf[n][1], p2 = sf[n][2], p3 = sf[n][3];
                __nv_bfloat162 h01 = __floats2bfloat162_rn(p0, p1);
                __nv_bfloat162 h23 = __floats2bfloat162_rn(p2, p3);
                __nv_bfloat162 l01 = __floats2bfloat162_rn(
                    p0 - __bfloat162float(h01.x), p1 - __bfloat162float(h01.y));
                __nv_bfloat162 l23 = __floats2bfloat162_rn(
                    p2 - __bfloat162float(h23.x), p3 - __bfloat162float(h23.y));
                pfh[kv][0 + 2 * half] = *(uint32_t*)&h01;
                pfh[kv][1 + 2 * half] = *(uint32_t*)&h23;
                pfl[kv][0 + 2 * half] = *(uint32_t*)&l01;
                pfl[kv][1 + 2 * half] = *(uint32_t*)&l23;
            }
        }

        // ---- wait for V, then O += P V (trans ldmatrix) ----
        asm volatile("cp.async.wait_group 1;" ::: "memory");   // V(kt) ready
        __syncthreads();

#pragma unroll
        for (int dp = 0; dp < 8; dp++) {
#pragma unroll
            for (int kv = 0; kv < 4; kv++) {
                uint32_t ad = sbase ? 0 : 0;  // (no-op, keeps compiler quiet)
                (void)ad;
                uint32_t vbase = sbase + vLane
                               + (uint32_t)(kv * 16 * KSTR + dp * 16) * 2u;
                uint32_t vh[4], vl[4];
                LDSM4T(vh, vbase);
                LDSM4T(vl, vbase + (uint32_t)K_ELEMS * 2u);
                float* oc0 = Oacc[2 * dp];
                float* oc1 = Oacc[2 * dp + 1];
                mma_bf16(oc0, pfh[kv][0], pfh[kv][1], pfh[kv][2], pfh[kv][3], vl[0], vl[1]);
                mma_bf16(oc0, pfl[kv][0], pfl[kv][1], pfl[kv][2], pfl[kv][3], vh[0], vh[1]);
                mma_bf16(oc0, pfh[kv][0], pfh[kv][1], pfh[kv][2], pfh[kv][3], vh[0], vh[1]);
                mma_bf16(oc1, pfh[kv][0], pfh[kv][1], pfh[kv][2], pfh[kv][3], vl[2], vl[3]);
                mma_bf16(oc1, pfl[kv][0], pfl[kv][1], pfl[kv][2], pfl[kv][3], vh[2], vh[3]);
                mma_bf16(oc1, pfh[kv][0], pfh[kv][1], pfh[kv][2], pfh[kv][3], vh[2], vh[3]);
            }
        }
    }

    // ---- finalize: write bf16 hi/lo ----
    float liA = 1.0f / lA, liB = 1.0f / lB;
    const size_t rowA = (tokbase + qr + g) * D_MODEL + h * D_HEAD;
    const size_t rowB = (tokbase + qr + g + 8) * D_MODEL + h * D_HEAD;
#pragma unroll
    for (int d = 0; d < 16; d++) {
        float a0 = Oacc[d][0] * liA, a1 = Oacc[d][1] * liA;
        float b0 = Oacc[d][2] * liB, b1 = Oacc[d][3] * liB;
        __nv_bfloat162 hA = __floats2bfloat162_rn(a0, a1);
        __nv_bfloat162 lAv = __floats2bfloat162_rn(a0 - __bfloat162float(hA.x),
                                                   a1 - __bfloat162float(hA.y));
        __nv_bfloat162 hB = __floats2bfloat162_rn(b0, b1);
        __nv_bfloat162 lBv = __floats2bfloat162_rn(b0 - __bfloat162float(hB.x),
                                                   b1 - __bfloat162float(hB.y));
        *(__nv_bfloat162*)(Oh + rowA + d * 8 + 2 * tg) = hA;
        *(__nv_bfloat162*)(Ol + rowA + d * 8 + 2 * tg) = lAv;
        *(__nv_bfloat162*)(Oh + rowB + d * 8 + 2 * tg) = hB;
        *(__nv_bfloat162*)(Ol + rowB + d * 8 + 2 * tg) = lBv;
    }
#undef LOAD_K
#undef LOAD_V
}

// ---------------- host launch ----------------
extern "C" void kernel_launch(void* const* d_in, const int* in_sizes, int n_in,
                              void* d_out, int out_size)
{
    const float* x   = (const float*)d_in[0];
    const float* cosb= (const float*)d_in[1];
    const float* sinb= (const float*)d_in[2];
    const float* Wq  = (const float*)d_in[3];
    const float* bq  = (const float*)d_in[4];
    const float* Wk  = (const float*)d_in[5];
    const float* bk  = (const float*)d_in[6];
    const float* Wv  = (const float*)d_in[7];
    const float* bv  = (const float*)d_in[8];
    const float* qnw = (const float*)d_in[9];
    const float* knw = (const float*)d_in[10];
    const float* Wo  = (const float*)d_in[11];
    const float* bo  = (const float*)d_in[12];
    float* out = (float*)d_out;

    const int BT = in_sizes[0] / D_MODEL;    // 4096
    const int Bb = BT / T_SEQ;               // 2

    float *qp, *kp;
    cudaGetSymbolAddress((void**)&qp, g_q);
    cudaGetSymbolAddress((void**)&kp, g_k);
    __nv_bfloat16 *xh, *xl, *wh, *wl, *ah, *al, *qh, *ql, *kh, *kl, *vh, *vl;
    cudaGetSymbolAddress((void**)&xh, g_xh);
    cudaGetSymbolAddress((void**)&xl, g_xl);
    cudaGetSymbolAddress((void**)&wh, g_wh);
    cudaGetSymbolAddress((void**)&wl, g_wl);
    cudaGetSymbolAddress((void**)&ah, g_ah);
    cudaGetSymbolAddress((void**)&al, g_al);
    cudaGetSymbolAddress((void**)&qh, g_qh);
    cudaGetSymbolAddress((void**)&ql, g_ql);
    cudaGetSymbolAddress((void**)&kh, g_kh);
    cudaGetSymbolAddress((void**)&kl, g_kl);
    cudaGetSymbolAddress((void**)&vh, g_vh);
    cudaGetSymbolAddress((void**)&vl, g_vl);

    cudaFuncSetAttribute(gemm_bf16, cudaFuncAttributeMaxDynamicSharedMemorySize, GEMM_SMEM);
    cudaFuncSetAttribute(attn_tc, cudaFuncAttributeMaxDynamicSharedMemorySize, ATTN_SMEM);

    const int nX4 = BT * D_MODEL / 4;
    const int nW4 = D_MODEL * D_MODEL / 4;
    const size_t woff = (size_t)D_MODEL * D_MODEL;

    split_bf16<<<(nX4 + 255) / 256, 256>>>(x, xh, xl, nX4);
    dim3 ws((nW4 + 255) / 256, 4);
    split_bf16_w<<<ws, 256>>>(Wq, Wk, Wv, Wo, wh, wl, nW4);

    // fused QKV: bz 0 -> Q fp32, bz 1 -> K fp32, bz 2 -> V bf16 hi/lo
    dim3 gq(D_MODEL / TN, BT / TM, 3);   // (8, 32, 3)
    gemm_bf16<<<gq, 256, GEMM_SMEM>>>(xh, xl, wh, wl,
                                      bq, qp, bk, kp, bv, vh, vl,
                                      BT, D_MODEL, D_MODEL);

    const float qscale = 0.08838834764831845f * 1.4426950408889634f;
    dim3 rn(BT, 2);
    rmsnorm_rope_bf<<<rn, 256>>>(qp, kp, qnw, knw, cosb, sinb,
                                 qh, ql, kh, kl, qscale);

    dim3 adim(T_SEQ / AQ, N_HEADS, Bb);   // (32, 16, 2)
    attn_tc<<<adim, 128, ATTN_SMEM>>>(qh, ql, kh, kl, vh, vl, ah, al);

    dim3 go(D_MODEL / TN, BT / TM, 1);
    gemm_bf16<<<go, 256, GEMM_SMEM>>>(ah, al, wh + 3 * woff, wl + 3 * woff,
                                      bo, out, bo, out, bo, (__nv_bfloat16*)nullptr,
                                      (__nv_bfloat16*)nullptr,
                                      BT, D_MODEL, D_MODEL);
}